// round 13
// baseline (speedup 1.0000x reference)
#include <cuda_runtime.h>
#include <cuda_fp16.h>
#include <math.h>
#include <stdint.h>

// Problem constants
#define BB 8
#define CC 512
#define NN 2304          // 48*48
#define NPROJ 1536       // q(512) | interleaved k,v (1024)
#define NKV 1024         // interleaved pairs: col 2c=ekv_c, 2c+1=ek_c
#define MGT 144          // NN/16 m-groups
#define KOCT_P 32        // CC/16 k-octs (projection K)
#define KOCT_A 144       // NN/16 k-octs (attention K)
#define NP16_P 96        // NPROJ/16 n-pairs
#define NP16_A 64        // NKV/16 n-pairs

// ---------------------------------------------------------------------------
// Scratch — MMA-native layouts (R10/R12-validated).
// ---------------------------------------------------------------------------
__device__ uint4  g_x4 [(size_t)BB * KOCT_P * MGT * 32];
__device__ uint4  g_y4 [(size_t)BB * KOCT_P * MGT * 32];
__device__ uint4  g_eb4[(size_t)KOCT_A * MGT * 32];
__device__ uint4  g_w4 [(size_t)KOCT_P * NP16_P * 32];
__device__ uint4  g_kv4[(size_t)BB * KOCT_A * NP16_A * 32];
__device__ __half g_sqh[(size_t)BB * NN * CC];   // sigmoid(q) fp16 [b][i][c]

// ---------------------------------------------------------------------------
// Helpers
// ---------------------------------------------------------------------------
__device__ __forceinline__ uint32_t packh2(float lo, float hi) {
    __half2 h = __floats2half2_rn(lo, hi);
    return *reinterpret_cast<uint32_t*>(&h);
}

__device__ __forceinline__ void mma_f16(float c[4], const uint32_t* a,
                                        const uint32_t* b) {
    asm volatile(
        "mma.sync.aligned.m16n8k16.row.col.f32.f16.f16.f32 "
        "{%0,%1,%2,%3},{%4,%5,%6,%7},{%8,%9},{%0,%1,%2,%3};\n"
        : "+f"(c[0]), "+f"(c[1]), "+f"(c[2]), "+f"(c[3])
        : "r"(a[0]), "r"(a[1]), "r"(a[2]), "r"(a[3]), "r"(b[0]), "r"(b[1]));
}

__device__ __forceinline__ uint32_t smem_u32(const void* p) {
    uint32_t a;
    asm("{ .reg .u64 t; cvta.to.shared.u64 t, %1; cvt.u32.u64 %0, t; }"
        : "=r"(a) : "l"(p));
    return a;
}

__device__ __forceinline__ void cp16(uint32_t saddr, const void* gptr) {
    asm volatile("cp.async.cg.shared.global [%0], [%1], 16;"
                 :: "r"(saddr), "l"(gptr));
}
#define CP_COMMIT() asm volatile("cp.async.commit_group;" ::: "memory")
#define CP_WAIT(n)  asm volatile("cp.async.wait_group %0;" :: "n"(n) : "memory")

// ---------------------------------------------------------------------------
// prep_all (fused): block ranges
//   [0,4608) x->A-native  [4608,9216) y->A-native
//   [9216,9600) W->B-paired  [9600,12192) exp(pb)->A-native
// ---------------------------------------------------------------------------
#define PBLK_X  4608
#define PBLK_W  384
#define PBLK_EB 2592
#define PREP_BLOCKS (2 * PBLK_X + PBLK_W + PBLK_EB)   // 12192

__global__ void __launch_bounds__(256)
prep_all(const float* __restrict__ x, const float* __restrict__ y,
         const float* __restrict__ Wq, const float* __restrict__ Wk,
         const float* __restrict__ Wv, const float* __restrict__ pb) {
    __shared__ float s[16][132];
    const int tid = threadIdx.x;
    const int blk = blockIdx.x;

    if (blk < 2 * PBLK_X) {
        const bool isx = blk < PBLK_X;
        const float* src = isx ? x : y;
        uint4* dst = isx ? g_x4 : g_y4;
        int v = isx ? blk : blk - PBLK_X;
        int b = v / 576, rem = v % 576;
        int koct = rem / 18, iblk = rem % 18;
        int i0 = iblk * 128, c0 = koct * 16;
        #pragma unroll
        for (int r = 0; r < 2; r++) {
            int idx = tid + r * 256;
            int row = idx >> 5, col4 = (idx & 31) << 2;
            float4 f = *(const float4*)(src + ((size_t)(b * CC + c0 + row)) * NN + i0 + col4);
            *(float4*)(&s[row][col4]) = f;
        }
        __syncthreads();
        const int mg = tid >> 5, lane = tid & 31, lr = lane >> 2, lq = lane & 3;
        const int m = mg * 16 + lr;
        uint4 o;
        o.x = packh2(s[2 * lq][m],     s[2 * lq + 1][m]);
        o.y = packh2(s[2 * lq][m + 8], s[2 * lq + 1][m + 8]);
        o.z = packh2(s[2 * lq + 8][m],     s[2 * lq + 9][m]);
        o.w = packh2(s[2 * lq + 8][m + 8], s[2 * lq + 9][m + 8]);
        dst[(((size_t)b * KOCT_P + koct) * MGT + iblk * 8 + mg) * 32 + lane] = o;
    } else if (blk < 2 * PBLK_X + PBLK_W) {
        int idx = (blk - 2 * PBLK_X) * 256 + tid;
        int lane = idx & 31;
        int p    = (idx >> 5) % NP16_P;
        int koct = idx / (NP16_P * 32);
        int lr = lane >> 2, lq = lane & 3;
        int k0 = koct * 16 + 2 * lq;
        auto wval = [&](int n, int kk) -> float {
            const float* W;
            int c;
            if (n < 512) { W = Wq; c = n; }
            else {
                int m = n - 512;
                c = m >> 1;
                W = (m & 1) ? Wv : Wk;
            }
            return W[(size_t)c * CC + kk];
        };
        int ne = p * 16 + lr, no = ne + 8;
        uint4 o;
        o.x = packh2(wval(ne, k0),     wval(ne, k0 + 1));
        o.y = packh2(wval(ne, k0 + 8), wval(ne, k0 + 9));
        o.z = packh2(wval(no, k0),     wval(no, k0 + 1));
        o.w = packh2(wval(no, k0 + 8), wval(no, k0 + 9));
        g_w4[idx] = o;
    } else {
        int t = blk - (2 * PBLK_X + PBLK_W);
        int koct = t / 18, iblk = t % 18;
        int i0 = iblk * 128, j0 = koct * 16;
        #pragma unroll
        for (int r = 0; r < 2; r++) {
            int idx = tid + r * 256;
            int irow = idx >> 2, j4 = (idx & 3) << 2;
            float4 f = *(const float4*)(pb + (size_t)(i0 + irow) * NN + j0 + j4);
            s[j4 + 0][irow] = __expf(f.x);
            s[j4 + 1][irow] = __expf(f.y);
            s[j4 + 2][irow] = __expf(f.z);
            s[j4 + 3][irow] = __expf(f.w);
        }
        __syncthreads();
        const int mg = tid >> 5, lane = tid & 31, lr = lane >> 2, lq = lane & 3;
        const int m = mg * 16 + lr;
        uint4 o;
        o.x = packh2(s[2 * lq][m],     s[2 * lq + 1][m]);
        o.y = packh2(s[2 * lq][m + 8], s[2 * lq + 1][m + 8]);
        o.z = packh2(s[2 * lq + 8][m],     s[2 * lq + 9][m]);
        o.w = packh2(s[2 * lq + 8][m + 8], s[2 * lq + 9][m + 8]);
        g_eb4[((size_t)koct * MGT + iblk * 8 + mg) * 32 + lane] = o;
    }
}

// ---------------------------------------------------------------------------
// fp16 GEMM core: BM=128 BN=128, chunk = 4 k-octs (64 k), 256 thr,
// warps 4(m) x 2(n), warp tile 32x64, 3-stage ring, 2 CTAs/SM.
// cp.async issue interleaved into the ka loop (2 per step, 1 commit/chunk).
// ---------------------------------------------------------------------------
#define STG 3
#define A_ST 16384
#define B_ST 16384
#define GEMM_SMEM (STG * (A_ST + B_ST))   // 98304 B

template <int MODE>
__global__ void __launch_bounds__(256, 2)
gemm_f16(const float* __restrict__ bq, const float* __restrict__ bk,
         const float* __restrict__ bv, float* __restrict__ out) {
    extern __shared__ char smem[];
    const uint32_t smb = smem_u32(smem);

    const int b  = blockIdx.z;
    const int m0 = blockIdx.x * 128;
    const int n0 = blockIdx.y * 128;
    const int tid = threadIdx.x;

    const uint4* Ag;
    const uint4* Bg;
    int NP16, nch;
    if (MODE == 0) {
        Ag = ((blockIdx.y < 4) ? g_x4 : g_y4) + (size_t)b * KOCT_P * MGT * 32;
        Bg = g_w4;
        NP16 = NP16_P; nch = KOCT_P / 4;         // 8
    } else {
        Ag = g_eb4;
        Bg = g_kv4 + (size_t)b * KOCT_A * NP16_A * 32;
        NP16 = NP16_A; nch = KOCT_A / 4;         // 36
    }
    const int mg0 = m0 >> 4;
    const int np0 = n0 >> 4;

    const int wid = tid >> 5;
    const int mwg = (wid & 3) * 2;
    const int nw  = (wid >> 2) * 64;
    const int nwp = nw >> 4;
    const int lane = tid & 31;
    const int lq = lane & 3;
    const int lr = lane >> 2;

    // Issue one koct-slice (A+B) of chunk ch into stage st
    auto issueSlice = [&](int ch, int st, int r) {
        int ko = ch * 4 + r;
        cp16(smb + st * A_ST + r * 4096 + tid * 16,
             Ag + ((size_t)ko * MGT + mg0) * 32 + tid);
        cp16(smb + STG * A_ST + st * B_ST + r * 4096 + tid * 16,
             Bg + ((size_t)ko * NP16 + np0) * 32 + tid);
    };

    float acc[2][8][4];
    #pragma unroll
    for (int i = 0; i < 2; i++)
        #pragma unroll
        for (int j = 0; j < 8; j++)
            #pragma unroll
            for (int l = 0; l < 4; l++) acc[i][j][l] = 0.f;

    // Prologue: chunks 0, 1 in flight
    #pragma unroll
    for (int s = 0; s < STG - 1; s++) {
        #pragma unroll
        for (int r = 0; r < 4; r++) issueSlice(s, s, r);
        CP_COMMIT();
    }

    int st = 0, nst = STG - 1;
    for (int c = 0; c < nch; c++) {
        CP_WAIT(STG - 2);
        __syncthreads();
        const bool more = (c + STG - 1) < nch;
        const int nc = c + STG - 1;

        const uint4* As4 = (const uint4*)(smem + st * A_ST);
        const uint4* Bs4 = (const uint4*)(smem + STG * A_ST + st * B_ST);
        #pragma unroll
        for (int ka = 0; ka < 4; ka++) {
            if (more) issueSlice(nc, nst, ka);     // spread the 8 cp16 across ka
            uint4 af0 = As4[ka * 256 + mwg * 32 + lane];
            uint4 af1 = As4[ka * 256 + (mwg + 1) * 32 + lane];
            uint4 bp[4];
            #pragma unroll
            for (int pw = 0; pw < 4; pw++)
                bp[pw] = Bs4[ka * 256 + (nwp + pw) * 32 + lane];
            #pragma unroll
            for (int pw = 0; pw < 4; pw++) {
                mma_f16(acc[0][2 * pw],     (const uint32_t*)&af0, &bp[pw].x);
                mma_f16(acc[0][2 * pw + 1], (const uint32_t*)&af0, &bp[pw].z);
                mma_f16(acc[1][2 * pw],     (const uint32_t*)&af1, &bp[pw].x);
                mma_f16(acc[1][2 * pw + 1], (const uint32_t*)&af1, &bp[pw].z);
            }
        }
        CP_COMMIT();
        st++; if (st == STG) st = 0;
        nst++; if (nst == STG) nst = 0;
    }

    // ------------------------------- Epilogues -----------------------------
    const int mw = (wid & 3) * 32;
    if (MODE == 0) {
        if (n0 < 512) {
            __half* sq = g_sqh + (size_t)b * NN * CC;
            #pragma unroll
            for (int mi = 0; mi < 2; mi++) {
                #pragma unroll
                for (int ni = 0; ni < 8; ni++) {
                    int row = m0 + mw + 16 * mi + lr;
                    int col = n0 + nw + 8 * ni + 2 * lq;
                    float b0 = bq[col], b1 = bq[col + 1];
                    float* a = acc[mi][ni];
                    float s00 = __fdividef(1.f, 1.f + __expf(-(a[0] + b0)));
                    float s01 = __fdividef(1.f, 1.f + __expf(-(a[1] + b1)));
                    float s10 = __fdividef(1.f, 1.f + __expf(-(a[2] + b0)));
                    float s11 = __fdividef(1.f, 1.f + __expf(-(a[3] + b1)));
                    *(uint32_t*)(sq + (size_t)row * CC + col) = packh2(s00, s01);
                    *(uint32_t*)(sq + (size_t)(row + 8) * CC + col) = packh2(s10, s11);
                }
            }
        } else {
            // kv region -> attn B-paired [koct_j][pair][lane]
            uint4* kvh = g_kv4 + (size_t)b * KOCT_A * NP16_A * 32;
            const bool evenR = (lr & 1) == 0;
            const int t = lr >> 1;
            #pragma unroll
            for (int mi = 0; mi < 2; mi++) {
                int mb = m0 + mw + 16 * mi;
                int koct = mb >> 4;
                #pragma unroll
                for (int np = 0; np < 4; np++) {
                    int col_e = n0 + nw + 16 * np + 2 * lq - 512;
                    int ch_e = col_e >> 1;
                    int ch_o = ch_e + 4;
                    float* ae = acc[mi][2 * np];
                    float* ao = acc[mi][2 * np + 1];
                    float bk_e = bk[ch_e], bv_e = bv[ch_e];
                    float bk_o = bk[ch_o], bv_o = bv[ch_o];
                    float e0e  = __expf(ae[0] + bk_e);
                    float ev0e = e0e * (ae[1] + bv_e);
                    float e1e  = __expf(ae[2] + bk_e);
                    float ev1e = e1e * (ae[3] + bv_e);
                    float e0o  = __expf(ao[0] + bk_o);
                    float ev0o = e0o * (ao[1] + bv_o);
                    float e1o  = __expf(ao[2] + bk_o);
                    float ev1o = e1o * (ao[3] + bv_o);
                    float pe0e  = __shfl_xor_sync(0xffffffffu, e0e, 4);
                    float pev0e = __shfl_xor_sync(0xffffffffu, ev0e, 4);
                    float pe1e  = __shfl_xor_sync(0xffffffffu, e1e, 4);
                    float pev1e = __shfl_xor_sync(0xffffffffu, ev1e, 4);
                    float pe0o  = __shfl_xor_sync(0xffffffffu, e0o, 4);
                    float pev0o = __shfl_xor_sync(0xffffffffu, ev0o, 4);
                    float pe1o  = __shfl_xor_sync(0xffffffffu, e1o, 4);
                    float pev1o = __shfl_xor_sync(0xffffffffu, ev1o, 4);
                    if (evenR) {
                        int p = col_e >> 4;
                        int lane_e = (col_e & 7) * 4 + t;
                        uint4 wkv, wek;
                        wkv.x = packh2(ev0e, pev0e);
                        wkv.y = packh2(ev1e, pev1e);
                        wkv.z = packh2(ev0o, pev0o);
                        wkv.w = packh2(ev1o, pev1o);
                        wek.x = packh2(e0e, pe0e);
                        wek.y = packh2(e1e, pe1e);
                        wek.z = packh2(e0o, pe0o);
                        wek.w = packh2(e1o, pe1o);
                        kvh[((size_t)koct * NP16_A + p) * 32 + lane_e]     = wkv;
                        kvh[((size_t)koct * NP16_A + p) * 32 + lane_e + 4] = wek;
                    }
                }
            }
        }
    } else {
        // attn: even col = num, odd = den -> sq * num/den -> transpose -> out
        __syncthreads();
        float* so = (float*)smem;     // [c_local 0..63][m_local 0..127] stride 136
        const __half* sq = g_sqh + (size_t)b * NN * CC;
        const int gc0 = n0 >> 1;
        #pragma unroll
        for (int mi = 0; mi < 2; mi++) {
            #pragma unroll
            for (int ni = 0; ni < 8; ni++) {
                int rowm = mw + 16 * mi + lr;
                int cl = (nw >> 1) + 4 * ni + lq;
                int gi = m0 + rowm;
                int gc = gc0 + cl;
                float* a = acc[mi][ni];
                float s0 = __half2float(sq[(size_t)gi * CC + gc]);
                float s1 = __half2float(sq[(size_t)(gi + 8) * CC + gc]);
                so[cl * 136 + rowm]     = s0 * __fdividef(a[0], a[1]);
                so[cl * 136 + rowm + 8] = s1 * __fdividef(a[2], a[3]);
            }
        }
        __syncthreads();
        float* o = out + (size_t)b * CC * NN;
        #pragma unroll
        for (int r2 = 0; r2 < 8; r2++) {
            int v = tid + r2 * 256;
            int cl = v >> 5, m4 = (v & 31) << 2;
            float4 val = *(float4*)(so + cl * 136 + m4);
            *(float4*)(o + (size_t)(gc0 + cl) * NN + m0 + m4) = val;
        }
    }
}

// ---------------------------------------------------------------------------
// Launch.  Order: 0 prep_all, 1 proj, 2 attn
// ---------------------------------------------------------------------------
extern "C" void kernel_launch(void* const* d_in, const int* in_sizes, int n_in,
                              void* d_out, int out_size) {
    const float* x  = (const float*)d_in[0];
    const float* y  = (const float*)d_in[1];
    const float* Wq = (const float*)d_in[2];
    const float* bq = (const float*)d_in[3];
    const float* Wk = (const float*)d_in[4];
    const float* bk = (const float*)d_in[5];
    const float* Wv = (const float*)d_in[6];
    const float* bv = (const float*)d_in[7];
    const float* pb = (const float*)d_in[8];
    float* out = (float*)d_out;

    static bool attr_done = false;
    if (!attr_done) {
        cudaFuncSetAttribute(gemm_f16<0>,
                             cudaFuncAttributeMaxDynamicSharedMemorySize, GEMM_SMEM);
        cudaFuncSetAttribute(gemm_f16<1>,
                             cudaFuncAttributeMaxDynamicSharedMemorySize, GEMM_SMEM);
        attr_done = true;
    }

    // 0) all operand prep in one launch
    prep_all<<<PREP_BLOCKS, 256>>>(x, y, Wq, Wk, Wv, pb);

    // 1) fused projection GEMM -> g_sqh (fp16), g_kv4 (attn B-paired)
    {
        dim3 g(NN / 128, NPROJ / 128, BB);   // (18, 12, 8)
        gemm_f16<0><<<g, 256, GEMM_SMEM>>>(bq, bk, bv, nullptr);
    }

    // 2) attention GEMM + fused final epilogue -> out
    {
        dim3 g(NN / 128, NKV / 128, BB);     // (18, 8, 8)
        gemm_f16<1><<<g, 256, GEMM_SMEM>>>(bq, bk, bv, out);
    }
}

// round 14
// speedup vs baseline: 1.0182x; 1.0182x over previous
#include <cuda_runtime.h>
#include <cuda_fp16.h>
#include <math.h>
#include <stdint.h>

// Problem constants
#define BB 8
#define CC 512
#define NN 2304          // 48*48
#define NPROJ 1536       // q(512) | interleaved k,v (1024)
#define NKV 1024         // interleaved pairs: col 2c=ekv_c, 2c+1=ek_c
#define MGT 144          // NN/16 m-groups
#define KOCT_P 32        // CC/16 k-octs (projection K)
#define KOCT_A 144       // NN/16 k-octs (attention K)
#define NP16_P 96        // NPROJ/16 n-pairs
#define NP16_A 64        // NKV/16 n-pairs

// ---------------------------------------------------------------------------
// Scratch — MMA-native layouts (R10/R12-validated).
// ---------------------------------------------------------------------------
__device__ uint4  g_x4 [(size_t)BB * KOCT_P * MGT * 32];
__device__ uint4  g_y4 [(size_t)BB * KOCT_P * MGT * 32];
__device__ uint4  g_eb4[(size_t)KOCT_A * MGT * 32];
__device__ uint4  g_w4 [(size_t)KOCT_P * NP16_P * 32];
__device__ uint4  g_kv4[(size_t)BB * KOCT_A * NP16_A * 32];
__device__ __half g_sqh[(size_t)BB * NN * CC];   // sigmoid(q) fp16 [b][i][c]

// ---------------------------------------------------------------------------
// Helpers
// ---------------------------------------------------------------------------
__device__ __forceinline__ uint32_t packh2(float lo, float hi) {
    __half2 h = __floats2half2_rn(lo, hi);
    return *reinterpret_cast<uint32_t*>(&h);
}

__device__ __forceinline__ void mma_f16(float c[4], const uint32_t* a,
                                        const uint32_t* b) {
    asm volatile(
        "mma.sync.aligned.m16n8k16.row.col.f32.f16.f16.f32 "
        "{%0,%1,%2,%3},{%4,%5,%6,%7},{%8,%9},{%0,%1,%2,%3};\n"
        : "+f"(c[0]), "+f"(c[1]), "+f"(c[2]), "+f"(c[3])
        : "r"(a[0]), "r"(a[1]), "r"(a[2]), "r"(a[3]), "r"(b[0]), "r"(b[1]));
}

__device__ __forceinline__ uint32_t smem_u32(const void* p) {
    uint32_t a;
    asm("{ .reg .u64 t; cvta.to.shared.u64 t, %1; cvt.u32.u64 %0, t; }"
        : "=r"(a) : "l"(p));
    return a;
}

__device__ __forceinline__ void cp16(uint32_t saddr, const void* gptr) {
    asm volatile("cp.async.cg.shared.global [%0], [%1], 16;"
                 :: "r"(saddr), "l"(gptr));
}
#define CP_COMMIT() asm volatile("cp.async.commit_group;" ::: "memory")
#define CP_WAIT(n)  asm volatile("cp.async.wait_group %0;" :: "n"(n) : "memory")

// ---------------------------------------------------------------------------
// prep_all (fused): block ranges
//   [0,4608) x->A-native  [4608,9216) y->A-native
//   [9216,9600) W->B-paired  [9600,12192) exp(pb)->A-native
// ---------------------------------------------------------------------------
#define PBLK_X  4608
#define PBLK_W  384
#define PBLK_EB 2592
#define PREP_BLOCKS (2 * PBLK_X + PBLK_W + PBLK_EB)   // 12192

__global__ void __launch_bounds__(256)
prep_all(const float* __restrict__ x, const float* __restrict__ y,
         const float* __restrict__ Wq, const float* __restrict__ Wk,
         const float* __restrict__ Wv, const float* __restrict__ pb) {
    __shared__ float s[16][132];
    const int tid = threadIdx.x;
    const int blk = blockIdx.x;

    if (blk < 2 * PBLK_X) {
        const bool isx = blk < PBLK_X;
        const float* src = isx ? x : y;
        uint4* dst = isx ? g_x4 : g_y4;
        int v = isx ? blk : blk - PBLK_X;
        int b = v / 576, rem = v % 576;
        int koct = rem / 18, iblk = rem % 18;
        int i0 = iblk * 128, c0 = koct * 16;
        #pragma unroll
        for (int r = 0; r < 2; r++) {
            int idx = tid + r * 256;
            int row = idx >> 5, col4 = (idx & 31) << 2;
            float4 f = *(const float4*)(src + ((size_t)(b * CC + c0 + row)) * NN + i0 + col4);
            *(float4*)(&s[row][col4]) = f;
        }
        __syncthreads();
        const int mg = tid >> 5, lane = tid & 31, lr = lane >> 2, lq = lane & 3;
        const int m = mg * 16 + lr;
        uint4 o;
        o.x = packh2(s[2 * lq][m],     s[2 * lq + 1][m]);
        o.y = packh2(s[2 * lq][m + 8], s[2 * lq + 1][m + 8]);
        o.z = packh2(s[2 * lq + 8][m],     s[2 * lq + 9][m]);
        o.w = packh2(s[2 * lq + 8][m + 8], s[2 * lq + 9][m + 8]);
        dst[(((size_t)b * KOCT_P + koct) * MGT + iblk * 8 + mg) * 32 + lane] = o;
    } else if (blk < 2 * PBLK_X + PBLK_W) {
        int idx = (blk - 2 * PBLK_X) * 256 + tid;
        int lane = idx & 31;
        int p    = (idx >> 5) % NP16_P;
        int koct = idx / (NP16_P * 32);
        int lr = lane >> 2, lq = lane & 3;
        int k0 = koct * 16 + 2 * lq;
        auto wval = [&](int n, int kk) -> float {
            const float* W;
            int c;
            if (n < 512) { W = Wq; c = n; }
            else {
                int m = n - 512;
                c = m >> 1;
                W = (m & 1) ? Wv : Wk;
            }
            return W[(size_t)c * CC + kk];
        };
        int ne = p * 16 + lr, no = ne + 8;
        uint4 o;
        o.x = packh2(wval(ne, k0),     wval(ne, k0 + 1));
        o.y = packh2(wval(ne, k0 + 8), wval(ne, k0 + 9));
        o.z = packh2(wval(no, k0),     wval(no, k0 + 1));
        o.w = packh2(wval(no, k0 + 8), wval(no, k0 + 9));
        g_w4[idx] = o;
    } else {
        int t = blk - (2 * PBLK_X + PBLK_W);
        int koct = t / 18, iblk = t % 18;
        int i0 = iblk * 128, j0 = koct * 16;
        #pragma unroll
        for (int r = 0; r < 2; r++) {
            int idx = tid + r * 256;
            int irow = idx >> 2, j4 = (idx & 3) << 2;
            float4 f = *(const float4*)(pb + (size_t)(i0 + irow) * NN + j0 + j4);
            s[j4 + 0][irow] = __expf(f.x);
            s[j4 + 1][irow] = __expf(f.y);
            s[j4 + 2][irow] = __expf(f.z);
            s[j4 + 3][irow] = __expf(f.w);
        }
        __syncthreads();
        const int mg = tid >> 5, lane = tid & 31, lr = lane >> 2, lq = lane & 3;
        const int m = mg * 16 + lr;
        uint4 o;
        o.x = packh2(s[2 * lq][m],     s[2 * lq + 1][m]);
        o.y = packh2(s[2 * lq][m + 8], s[2 * lq + 1][m + 8]);
        o.z = packh2(s[2 * lq + 8][m],     s[2 * lq + 9][m]);
        o.w = packh2(s[2 * lq + 8][m + 8], s[2 * lq + 9][m + 8]);
        g_eb4[((size_t)koct * MGT + iblk * 8 + mg) * 32 + lane] = o;
    }
}

// ---------------------------------------------------------------------------
// fp16 GEMM core: BM=128 BN=128, chunk = 4 k-octs (64 k), 256 thr,
// warps 4(m) x 2(n), warp tile 32x64, 3-stage ring (burst issue, R12 form),
// 2 CTAs/SM.  Per ka-step: 6x LDS.128 feed 16 HMMAs.
// ---------------------------------------------------------------------------
#define STG 3
#define A_ST 16384
#define B_ST 16384
#define GEMM_SMEM (STG * (A_ST + B_ST))   // 98304 B

template <int MODE>
__global__ void __launch_bounds__(256, 2)
gemm_f16(const float* __restrict__ bq, const float* __restrict__ bk,
         const float* __restrict__ bv, float* __restrict__ out) {
    extern __shared__ char smem[];
    const uint32_t smb = smem_u32(smem);

    const int b  = blockIdx.z;
    const int m0 = blockIdx.x * 128;
    const int n0 = blockIdx.y * 128;
    const int tid = threadIdx.x;

    const uint4* Ag;
    const uint4* Bg;
    int NP16, nch;
    if (MODE == 0) {
        Ag = ((blockIdx.y < 4) ? g_x4 : g_y4) + (size_t)b * KOCT_P * MGT * 32;
        Bg = g_w4;
        NP16 = NP16_P; nch = KOCT_P / 4;         // 8
    } else {
        Ag = g_eb4;
        Bg = g_kv4 + (size_t)b * KOCT_A * NP16_A * 32;
        NP16 = NP16_A; nch = KOCT_A / 4;         // 36
    }
    const int mg0 = m0 >> 4;
    const int np0 = n0 >> 4;

    const int wid = tid >> 5;
    const int mwg = (wid & 3) * 2;
    const int nw  = (wid >> 2) * 64;
    const int nwp = nw >> 4;
    const int lane = tid & 31;
    const int lq = lane & 3;
    const int lr = lane >> 2;

    auto loadAsync = [&](int ch, int st) {
        const uint32_t sA = smb + st * A_ST;
        const uint32_t sB = smb + STG * A_ST + st * B_ST;
        #pragma unroll
        for (int r = 0; r < 4; r++) {
            int ko = ch * 4 + r;
            cp16(sA + r * 4096 + tid * 16,
                 Ag + ((size_t)ko * MGT + mg0) * 32 + tid);
            cp16(sB + r * 4096 + tid * 16,
                 Bg + ((size_t)ko * NP16 + np0) * 32 + tid);
        }
    };

    float acc[2][8][4];
    #pragma unroll
    for (int i = 0; i < 2; i++)
        #pragma unroll
        for (int j = 0; j < 8; j++)
            #pragma unroll
            for (int l = 0; l < 4; l++) acc[i][j][l] = 0.f;

    #pragma unroll
    for (int s = 0; s < STG - 1; s++) {
        loadAsync(s, s);
        CP_COMMIT();
    }

    int st = 0;
    for (int c = 0; c < nch; c++) {
        CP_WAIT(STG - 2);
        __syncthreads();
        if (c + STG - 1 < nch) loadAsync(c + STG - 1, (c + STG - 1) % STG);
        CP_COMMIT();

        const uint4* As4 = (const uint4*)(smem + st * A_ST);
        const uint4* Bs4 = (const uint4*)(smem + STG * A_ST + st * B_ST);
        #pragma unroll
        for (int ka = 0; ka < 4; ka++) {
            uint4 af0 = As4[ka * 256 + mwg * 32 + lane];
            uint4 af1 = As4[ka * 256 + (mwg + 1) * 32 + lane];
            uint4 bp[4];
            #pragma unroll
            for (int pw = 0; pw < 4; pw++)
                bp[pw] = Bs4[ka * 256 + (nwp + pw) * 32 + lane];
            #pragma unroll
            for (int pw = 0; pw < 4; pw++) {
                mma_f16(acc[0][2 * pw],     (const uint32_t*)&af0, &bp[pw].x);
                mma_f16(acc[0][2 * pw + 1], (const uint32_t*)&af0, &bp[pw].z);
                mma_f16(acc[1][2 * pw],     (const uint32_t*)&af1, &bp[pw].x);
                mma_f16(acc[1][2 * pw + 1], (const uint32_t*)&af1, &bp[pw].z);
            }
        }
        st++;
        if (st == STG) st = 0;
    }

    // ------------------------------- Epilogues -----------------------------
    const int mw = (wid & 3) * 32;
    if (MODE == 0) {
        if (n0 < 512) {
            __half* sq = g_sqh + (size_t)b * NN * CC;
            #pragma unroll
            for (int mi = 0; mi < 2; mi++) {
                #pragma unroll
                for (int ni = 0; ni < 8; ni++) {
                    int row = m0 + mw + 16 * mi + lr;
                    int col = n0 + nw + 8 * ni + 2 * lq;
                    float b0 = bq[col], b1 = bq[col + 1];
                    float* a = acc[mi][ni];
                    float s00 = __fdividef(1.f, 1.f + __expf(-(a[0] + b0)));
                    float s01 = __fdividef(1.f, 1.f + __expf(-(a[1] + b1)));
                    float s10 = __fdividef(1.f, 1.f + __expf(-(a[2] + b0)));
                    float s11 = __fdividef(1.f, 1.f + __expf(-(a[3] + b1)));
                    *(uint32_t*)(sq + (size_t)row * CC + col) = packh2(s00, s01);
                    *(uint32_t*)(sq + (size_t)(row + 8) * CC + col) = packh2(s10, s11);
                }
            }
        } else {
            // kv region -> attn B-paired [koct_j][pair][lane]
            uint4* kvh = g_kv4 + (size_t)b * KOCT_A * NP16_A * 32;
            const bool evenR = (lr & 1) == 0;
            const int t = lr >> 1;
            #pragma unroll
            for (int mi = 0; mi < 2; mi++) {
                int mb = m0 + mw + 16 * mi;
                int koct = mb >> 4;
                #pragma unroll
                for (int np = 0; np < 4; np++) {
                    int col_e = n0 + nw + 16 * np + 2 * lq - 512;
                    int ch_e = col_e >> 1;
                    int ch_o = ch_e + 4;
                    float* ae = acc[mi][2 * np];
                    float* ao = acc[mi][2 * np + 1];
                    float bk_e = bk[ch_e], bv_e = bv[ch_e];
                    float bk_o = bk[ch_o], bv_o = bv[ch_o];
                    float e0e  = __expf(ae[0] + bk_e);
                    float ev0e = e0e * (ae[1] + bv_e);
                    float e1e  = __expf(ae[2] + bk_e);
                    float ev1e = e1e * (ae[3] + bv_e);
                    float e0o  = __expf(ao[0] + bk_o);
                    float ev0o = e0o * (ao[1] + bv_o);
                    float e1o  = __expf(ao[2] + bk_o);
                    float ev1o = e1o * (ao[3] + bv_o);
                    float pe0e  = __shfl_xor_sync(0xffffffffu, e0e, 4);
                    float pev0e = __shfl_xor_sync(0xffffffffu, ev0e, 4);
                    float pe1e  = __shfl_xor_sync(0xffffffffu, e1e, 4);
                    float pev1e = __shfl_xor_sync(0xffffffffu, ev1e, 4);
                    float pe0o  = __shfl_xor_sync(0xffffffffu, e0o, 4);
                    float pev0o = __shfl_xor_sync(0xffffffffu, ev0o, 4);
                    float pe1o  = __shfl_xor_sync(0xffffffffu, e1o, 4);
                    float pev1o = __shfl_xor_sync(0xffffffffu, ev1o, 4);
                    if (evenR) {
                        int p = col_e >> 4;
                        int lane_e = (col_e & 7) * 4 + t;
                        uint4 wkv, wek;
                        wkv.x = packh2(ev0e, pev0e);
                        wkv.y = packh2(ev1e, pev1e);
                        wkv.z = packh2(ev0o, pev0o);
                        wkv.w = packh2(ev1o, pev1o);
                        wek.x = packh2(e0e, pe0e);
                        wek.y = packh2(e1e, pe1e);
                        wek.z = packh2(e0o, pe0o);
                        wek.w = packh2(e1o, pe1o);
                        kvh[((size_t)koct * NP16_A + p) * 32 + lane_e]     = wkv;
                        kvh[((size_t)koct * NP16_A + p) * 32 + lane_e + 4] = wek;
                    }
                }
            }
        }
    } else {
        // attn: even col = num, odd = den -> sq * num/den -> transpose -> out
        // Stage sq tile coalesced into smem first (was 16 scattered 2B loads/thr).
        __syncthreads();
        float* so  = (float*)smem;               // [c_local 0..63][m 0..127] str 136
        float* sqs = (float*)(smem + 34816);     // [m 0..127][c_local 0..63] str 68
        const int gc0 = n0 >> 1;
        const __half* sqg = g_sqh + ((size_t)b * NN + m0) * CC + gc0;
        #pragma unroll
        for (int r2 = 0; r2 < 4; r2++) {
            int v = tid + r2 * 256;              // 1024 uint4: 128 rows x 8
            int row = v >> 3, c8 = (v & 7) * 8;
            uint4 h = *(const uint4*)(sqg + (size_t)row * CC + c8);
            const __half2* hp = (const __half2*)&h;
            float* dstp = sqs + row * 68 + c8;
            #pragma unroll
            for (int q = 0; q < 4; q++) {
                float2 f = __half22float2(hp[q]);
                dstp[2 * q]     = f.x;
                dstp[2 * q + 1] = f.y;
            }
        }
        __syncthreads();
        #pragma unroll
        for (int mi = 0; mi < 2; mi++) {
            #pragma unroll
            for (int ni = 0; ni < 8; ni++) {
                int rowm = mw + 16 * mi + lr;
                int cl = (nw >> 1) + 4 * ni + lq;
                float* a = acc[mi][ni];
                float s0 = sqs[rowm * 68 + cl];
                float s1 = sqs[(rowm + 8) * 68 + cl];
                so[cl * 136 + rowm]     = s0 * __fdividef(a[0], a[1]);
                so[cl * 136 + rowm + 8] = s1 * __fdividef(a[2], a[3]);
            }
        }
        __syncthreads();
        float* o = out + (size_t)b * CC * NN;
        #pragma unroll
        for (int r2 = 0; r2 < 8; r2++) {
            int v = tid + r2 * 256;
            int cl = v >> 5, m4 = (v & 31) << 2;
            float4 val = *(float4*)(so + cl * 136 + m4);
            *(float4*)(o + (size_t)(gc0 + cl) * NN + m0 + m4) = val;
        }
    }
}

// ---------------------------------------------------------------------------
// Launch.  Order: 0 prep_all, 1 proj, 2 attn
// ---------------------------------------------------------------------------
extern "C" void kernel_launch(void* const* d_in, const int* in_sizes, int n_in,
                              void* d_out, int out_size) {
    const float* x  = (const float*)d_in[0];
    const float* y  = (const float*)d_in[1];
    const float* Wq = (const float*)d_in[2];
    const float* bq = (const float*)d_in[3];
    const float* Wk = (const float*)d_in[4];
    const float* bk = (const float*)d_in[5];
    const float* Wv = (const float*)d_in[6];
    const float* bv = (const float*)d_in[7];
    const float* pb = (const float*)d_in[8];
    float* out = (float*)d_out;

    static bool attr_done = false;
    if (!attr_done) {
        cudaFuncSetAttribute(gemm_f16<0>,
                             cudaFuncAttributeMaxDynamicSharedMemorySize, GEMM_SMEM);
        cudaFuncSetAttribute(gemm_f16<1>,
                             cudaFuncAttributeMaxDynamicSharedMemorySize, GEMM_SMEM);
        attr_done = true;
    }

    // 0) all operand prep in one launch
    prep_all<<<PREP_BLOCKS, 256>>>(x, y, Wq, Wk, Wv, pb);

    // 1) fused projection GEMM -> g_sqh (fp16), g_kv4 (attn B-paired)
    {
        dim3 g(NN / 128, NPROJ / 128, BB);   // (18, 12, 8)
        gemm_f16<0><<<g, 256, GEMM_SMEM>>>(bq, bk, bv, nullptr);
    }

    // 2) attention GEMM + fused final epilogue -> out
    {
        dim3 g(NN / 128, NKV / 128, BB);     // (18, 8, 8)
        gemm_f16<1><<<g, 256, GEMM_SMEM>>>(bq, bk, bv, out);
    }
}

// round 15
// speedup vs baseline: 1.0625x; 1.0436x over previous
#include <cuda_runtime.h>
#include <cuda_fp16.h>
#include <math.h>
#include <stdint.h>

// Problem constants
#define BB 8
#define CC 512
#define NN 2304          // 48*48
#define NPROJ 1536       // q(512) | interleaved k,v (1024)
#define NKV 1024         // interleaved pairs: col 2c=ekv_c, 2c+1=ek_c
#define MGT 144          // NN/16 m-groups
#define KOCT_P 32        // CC/16 k-octs (projection K)
#define KOCT_A 144       // NN/16 k-octs (attention K)
#define NP16_P 96        // NPROJ/16 n-pairs
#define NP16_A 64        // NKV/16 n-pairs

// ---------------------------------------------------------------------------
// Scratch — MMA-native layouts (R10/R12-validated).
// ---------------------------------------------------------------------------
__device__ uint4  g_x4 [(size_t)BB * KOCT_P * MGT * 32];
__device__ uint4  g_y4 [(size_t)BB * KOCT_P * MGT * 32];
__device__ uint4  g_eb4[(size_t)KOCT_A * MGT * 32];
__device__ uint4  g_w4 [(size_t)KOCT_P * NP16_P * 32];
__device__ uint4  g_kv4[(size_t)BB * KOCT_A * NP16_A * 32];
__device__ __half g_sqh[(size_t)BB * NN * CC];   // sigmoid(q) fp16 [b][i][c]

// ---------------------------------------------------------------------------
// Helpers
// ---------------------------------------------------------------------------
__device__ __forceinline__ uint32_t packh2(float lo, float hi) {
    __half2 h = __floats2half2_rn(lo, hi);
    return *reinterpret_cast<uint32_t*>(&h);
}

__device__ __forceinline__ void mma_f16(float c[4], const uint32_t* a,
                                        const uint32_t* b) {
    asm volatile(
        "mma.sync.aligned.m16n8k16.row.col.f32.f16.f16.f32 "
        "{%0,%1,%2,%3},{%4,%5,%6,%7},{%8,%9},{%0,%1,%2,%3};\n"
        : "+f"(c[0]), "+f"(c[1]), "+f"(c[2]), "+f"(c[3])
        : "r"(a[0]), "r"(a[1]), "r"(a[2]), "r"(a[3]), "r"(b[0]), "r"(b[1]));
}

__device__ __forceinline__ uint32_t smem_u32(const void* p) {
    uint32_t a;
    asm("{ .reg .u64 t; cvta.to.shared.u64 t, %1; cvt.u32.u64 %0, t; }"
        : "=r"(a) : "l"(p));
    return a;
}

__device__ __forceinline__ void cp16(uint32_t saddr, const void* gptr) {
    asm volatile("cp.async.cg.shared.global [%0], [%1], 16;"
                 :: "r"(saddr), "l"(gptr));
}
#define CP_COMMIT() asm volatile("cp.async.commit_group;" ::: "memory")
#define CP_WAIT(n)  asm volatile("cp.async.wait_group %0;" :: "n"(n) : "memory")

// ---------------------------------------------------------------------------
// prep_all (fused): 2 k-octs per block for x/y/eb (MLP=4 per thread).
// Block ranges:
//   [0,2304) x   [2304,4608) y   [4608,4992) W   [4992,6288) exp(pb)
// ---------------------------------------------------------------------------
#define PBLK_X  2304
#define PBLK_W  384
#define PBLK_EB 1296
#define PREP_BLOCKS (2 * PBLK_X + PBLK_W + PBLK_EB)   // 6288

__global__ void __launch_bounds__(256)
prep_all(const float* __restrict__ x, const float* __restrict__ y,
         const float* __restrict__ Wq, const float* __restrict__ Wk,
         const float* __restrict__ Wv, const float* __restrict__ pb) {
    __shared__ float s[32][132];
    const int tid = threadIdx.x;
    const int blk = blockIdx.x;

    if (blk < 2 * PBLK_X) {
        // x/y -> A-native (k = channel), 2 k-octs (32 rows) per block
        const bool isx = blk < PBLK_X;
        const float* src = isx ? x : y;
        uint4* dst = isx ? g_x4 : g_y4;
        int v = isx ? blk : blk - PBLK_X;
        int b = v / 288, rem = v % 288;
        int kb2 = rem / 18, iblk = rem % 18;       // kb2: 2-koct group 0..15
        int i0 = iblk * 128, c0 = kb2 * 32;
        #pragma unroll
        for (int r = 0; r < 4; r++) {
            int idx = tid + r * 256;               // 1024 float4 = 32 rows x 32
            int row = idx >> 5, col4 = (idx & 31) << 2;
            float4 f = *(const float4*)(src + ((size_t)(b * CC + c0 + row)) * NN + i0 + col4);
            *(float4*)(&s[row][col4]) = f;
        }
        __syncthreads();
        const int mg = tid >> 5, lane = tid & 31, lr = lane >> 2, lq = lane & 3;
        const int m = mg * 16 + lr;
        #pragma unroll
        for (int t = 0; t < 2; t++) {
            int kb = 16 * t;
            uint4 o;
            o.x = packh2(s[kb + 2 * lq][m],     s[kb + 2 * lq + 1][m]);
            o.y = packh2(s[kb + 2 * lq][m + 8], s[kb + 2 * lq + 1][m + 8]);
            o.z = packh2(s[kb + 2 * lq + 8][m],     s[kb + 2 * lq + 9][m]);
            o.w = packh2(s[kb + 2 * lq + 8][m + 8], s[kb + 2 * lq + 9][m + 8]);
            int koct = kb2 * 2 + t;
            dst[(((size_t)b * KOCT_P + koct) * MGT + iblk * 8 + mg) * 32 + lane] = o;
        }
    } else if (blk < 2 * PBLK_X + PBLK_W) {
        // W -> B-paired, n = q | k,v interleaved
        int idx = (blk - 2 * PBLK_X) * 256 + tid;
        int lane = idx & 31;
        int p    = (idx >> 5) % NP16_P;
        int koct = idx / (NP16_P * 32);
        int lr = lane >> 2, lq = lane & 3;
        int k0 = koct * 16 + 2 * lq;
        auto wval = [&](int n, int kk) -> float {
            const float* W;
            int c;
            if (n < 512) { W = Wq; c = n; }
            else {
                int m = n - 512;
                c = m >> 1;
                W = (m & 1) ? Wv : Wk;
            }
            return W[(size_t)c * CC + kk];
        };
        int ne = p * 16 + lr, no = ne + 8;
        uint4 o;
        o.x = packh2(wval(ne, k0),     wval(ne, k0 + 1));
        o.y = packh2(wval(ne, k0 + 8), wval(ne, k0 + 9));
        o.z = packh2(wval(no, k0),     wval(no, k0 + 1));
        o.w = packh2(wval(no, k0 + 8), wval(no, k0 + 9));
        g_w4[idx] = o;
    } else {
        // exp(pb) -> A-native (m = i, k = j), 2 k-octs (32 j) per block
        int t = blk - (2 * PBLK_X + PBLK_W);
        int kb2 = t / 18, iblk = t % 18;           // kb2: 0..71
        int i0 = iblk * 128, j0 = kb2 * 32;
        #pragma unroll
        for (int r = 0; r < 4; r++) {
            int idx = tid + r * 256;               // 1024 float4 = 128 rows x 8
            int irow = idx >> 3, j4 = (idx & 7) << 2;
            float4 f = *(const float4*)(pb + (size_t)(i0 + irow) * NN + j0 + j4);
            s[j4 + 0][irow] = __expf(f.x);
            s[j4 + 1][irow] = __expf(f.y);
            s[j4 + 2][irow] = __expf(f.z);
            s[j4 + 3][irow] = __expf(f.w);
        }
        __syncthreads();
        const int mg = tid >> 5, lane = tid & 31, lr = lane >> 2, lq = lane & 3;
        const int m = mg * 16 + lr;
        #pragma unroll
        for (int tt = 0; tt < 2; tt++) {
            int kb = 16 * tt;
            uint4 o;
            o.x = packh2(s[kb + 2 * lq][m],     s[kb + 2 * lq + 1][m]);
            o.y = packh2(s[kb + 2 * lq][m + 8], s[kb + 2 * lq + 1][m + 8]);
            o.z = packh2(s[kb + 2 * lq + 8][m],     s[kb + 2 * lq + 9][m]);
            o.w = packh2(s[kb + 2 * lq + 8][m + 8], s[kb + 2 * lq + 9][m + 8]);
            int koct = kb2 * 2 + tt;
            g_eb4[((size_t)koct * MGT + iblk * 8 + mg) * 32 + lane] = o;
        }
    }
}

// ---------------------------------------------------------------------------
// fp16 GEMM core: BM=128 BN=128, chunk = 4 k-octs (64 k), 256 thr,
// warps 4(m) x 2(n), warp tile 32x64, 3-stage ring, 2 CTAs/SM.
// Steady/tail loop split (no per-chunk branch).
// ---------------------------------------------------------------------------
#define STG 3
#define A_ST 16384
#define B_ST 16384
#define GEMM_SMEM (STG * (A_ST + B_ST))   // 98304 B

template <int MODE>
__global__ void __launch_bounds__(256, 2)
gemm_f16(const float* __restrict__ bq, const float* __restrict__ bk,
         const float* __restrict__ bv, float* __restrict__ out) {
    extern __shared__ char smem[];
    const uint32_t smb = smem_u32(smem);

    const int b  = blockIdx.z;
    const int m0 = blockIdx.x * 128;
    const int n0 = blockIdx.y * 128;
    const int tid = threadIdx.x;

    const uint4* Ag;
    const uint4* Bg;
    int NP16, nch;
    if (MODE == 0) {
        Ag = ((blockIdx.y < 4) ? g_x4 : g_y4) + (size_t)b * KOCT_P * MGT * 32;
        Bg = g_w4;
        NP16 = NP16_P; nch = KOCT_P / 4;         // 8
    } else {
        Ag = g_eb4;
        Bg = g_kv4 + (size_t)b * KOCT_A * NP16_A * 32;
        NP16 = NP16_A; nch = KOCT_A / 4;         // 36
    }
    const int mg0 = m0 >> 4;
    const int np0 = n0 >> 4;

    const int wid = tid >> 5;
    const int mwg = (wid & 3) * 2;
    const int nw  = (wid >> 2) * 64;
    const int nwp = nw >> 4;
    const int lane = tid & 31;
    const int lq = lane & 3;
    const int lr = lane >> 2;

    auto loadAsync = [&](int ch, int st) {
        const uint32_t sA = smb + st * A_ST;
        const uint32_t sB = smb + STG * A_ST + st * B_ST;
        #pragma unroll
        for (int r = 0; r < 4; r++) {
            int ko = ch * 4 + r;
            cp16(sA + r * 4096 + tid * 16,
                 Ag + ((size_t)ko * MGT + mg0) * 32 + tid);
            cp16(sB + r * 4096 + tid * 16,
                 Bg + ((size_t)ko * NP16 + np0) * 32 + tid);
        }
    };

    float acc[2][8][4];
    #pragma unroll
    for (int i = 0; i < 2; i++)
        #pragma unroll
        for (int j = 0; j < 8; j++)
            #pragma unroll
            for (int l = 0; l < 4; l++) acc[i][j][l] = 0.f;

    auto compute = [&](int st) {
        const uint4* As4 = (const uint4*)(smem + st * A_ST);
        const uint4* Bs4 = (const uint4*)(smem + STG * A_ST + st * B_ST);
        #pragma unroll
        for (int ka = 0; ka < 4; ka++) {
            uint4 af0 = As4[ka * 256 + mwg * 32 + lane];
            uint4 af1 = As4[ka * 256 + (mwg + 1) * 32 + lane];
            uint4 bp[4];
            #pragma unroll
            for (int pw = 0; pw < 4; pw++)
                bp[pw] = Bs4[ka * 256 + (nwp + pw) * 32 + lane];
            #pragma unroll
            for (int pw = 0; pw < 4; pw++) {
                mma_f16(acc[0][2 * pw],     (const uint32_t*)&af0, &bp[pw].x);
                mma_f16(acc[0][2 * pw + 1], (const uint32_t*)&af0, &bp[pw].z);
                mma_f16(acc[1][2 * pw],     (const uint32_t*)&af1, &bp[pw].x);
                mma_f16(acc[1][2 * pw + 1], (const uint32_t*)&af1, &bp[pw].z);
            }
        }
    };

    #pragma unroll
    for (int s = 0; s < STG - 1; s++) {
        loadAsync(s, s);
        CP_COMMIT();
    }

    int st = 0, ldst = STG - 1;
    // Steady: prefetch chunk c+STG-1 while computing c
    for (int c = 0; c < nch - (STG - 1); c++) {
        CP_WAIT(STG - 2);
        __syncthreads();
        loadAsync(c + STG - 1, ldst);
        CP_COMMIT();
        compute(st);
        st++; if (st == STG) st = 0;
        ldst++; if (ldst == STG) ldst = 0;
    }
    // Tail: drain remaining STG-1 chunks
    #pragma unroll
    for (int c = 0; c < STG - 1; c++) {
        CP_WAIT(STG - 2);
        __syncthreads();
        CP_COMMIT();
        compute(st);
        st++; if (st == STG) st = 0;
    }

    // ------------------------------- Epilogues -----------------------------
    const int mw = (wid & 3) * 32;
    if (MODE == 0) {
        if (n0 < 512) {
            __half* sq = g_sqh + (size_t)b * NN * CC;
            #pragma unroll
            for (int mi = 0; mi < 2; mi++) {
                #pragma unroll
                for (int ni = 0; ni < 8; ni++) {
                    int row = m0 + mw + 16 * mi + lr;
                    int col = n0 + nw + 8 * ni + 2 * lq;
                    float b0 = bq[col], b1 = bq[col + 1];
                    float* a = acc[mi][ni];
                    float s00 = __fdividef(1.f, 1.f + __expf(-(a[0] + b0)));
                    float s01 = __fdividef(1.f, 1.f + __expf(-(a[1] + b1)));
                    float s10 = __fdividef(1.f, 1.f + __expf(-(a[2] + b0)));
                    float s11 = __fdividef(1.f, 1.f + __expf(-(a[3] + b1)));
                    *(uint32_t*)(sq + (size_t)row * CC + col) = packh2(s00, s01);
                    *(uint32_t*)(sq + (size_t)(row + 8) * CC + col) = packh2(s10, s11);
                }
            }
        } else {
            // kv region -> attn B-paired [koct_j][pair][lane]
            uint4* kvh = g_kv4 + (size_t)b * KOCT_A * NP16_A * 32;
            const bool evenR = (lr & 1) == 0;
            const int t = lr >> 1;
            #pragma unroll
            for (int mi = 0; mi < 2; mi++) {
                int mb = m0 + mw + 16 * mi;
                int koct = mb >> 4;
                #pragma unroll
                for (int np = 0; np < 4; np++) {
                    int col_e = n0 + nw + 16 * np + 2 * lq - 512;
                    int ch_e = col_e >> 1;
                    int ch_o = ch_e + 4;
                    float* ae = acc[mi][2 * np];
                    float* ao = acc[mi][2 * np + 1];
                    float bk_e = bk[ch_e], bv_e = bv[ch_e];
                    float bk_o = bk[ch_o], bv_o = bv[ch_o];
                    float e0e  = __expf(ae[0] + bk_e);
                    float ev0e = e0e * (ae[1] + bv_e);
                    float e1e  = __expf(ae[2] + bk_e);
                    float ev1e = e1e * (ae[3] + bv_e);
                    float e0o  = __expf(ao[0] + bk_o);
                    float ev0o = e0o * (ao[1] + bv_o);
                    float e1o  = __expf(ao[2] + bk_o);
                    float ev1o = e1o * (ao[3] + bv_o);
                    float pe0e  = __shfl_xor_sync(0xffffffffu, e0e, 4);
                    float pev0e = __shfl_xor_sync(0xffffffffu, ev0e, 4);
                    float pe1e  = __shfl_xor_sync(0xffffffffu, e1e, 4);
                    float pev1e = __shfl_xor_sync(0xffffffffu, ev1e, 4);
                    float pe0o  = __shfl_xor_sync(0xffffffffu, e0o, 4);
                    float pev0o = __shfl_xor_sync(0xffffffffu, ev0o, 4);
                    float pe1o  = __shfl_xor_sync(0xffffffffu, e1o, 4);
                    float pev1o = __shfl_xor_sync(0xffffffffu, ev1o, 4);
                    if (evenR) {
                        int p = col_e >> 4;
                        int lane_e = (col_e & 7) * 4 + t;
                        uint4 wkv, wek;
                        wkv.x = packh2(ev0e, pev0e);
                        wkv.y = packh2(ev1e, pev1e);
                        wkv.z = packh2(ev0o, pev0o);
                        wkv.w = packh2(ev1o, pev1o);
                        wek.x = packh2(e0e, pe0e);
                        wek.y = packh2(e1e, pe1e);
                        wek.z = packh2(e0o, pe0o);
                        wek.w = packh2(e1o, pe1o);
                        kvh[((size_t)koct * NP16_A + p) * 32 + lane_e]     = wkv;
                        kvh[((size_t)koct * NP16_A + p) * 32 + lane_e + 4] = wek;
                    }
                }
            }
        }
    } else {
        // attn: even col = num, odd = den -> sq * num/den -> transpose -> out
        __syncthreads();
        float* so  = (float*)smem;               // [c_local 0..63][m 0..127] str 136
        float* sqs = (float*)(smem + 34816);     // [m 0..127][c_local 0..63] str 68
        const int gc0 = n0 >> 1;
        const __half* sqg = g_sqh + ((size_t)b * NN + m0) * CC + gc0;
        #pragma unroll
        for (int r2 = 0; r2 < 4; r2++) {
            int v = tid + r2 * 256;              // 1024 uint4: 128 rows x 8
            int row = v >> 3, c8 = (v & 7) * 8;
            uint4 h = *(const uint4*)(sqg + (size_t)row * CC + c8);
            const __half2* hp = (const __half2*)&h;
            float* dstp = sqs + row * 68 + c8;
            #pragma unroll
            for (int q = 0; q < 4; q++) {
                float2 f = __half22float2(hp[q]);
                dstp[2 * q]     = f.x;
                dstp[2 * q + 1] = f.y;
            }
        }
        __syncthreads();
        #pragma unroll
        for (int mi = 0; mi < 2; mi++) {
            #pragma unroll
            for (int ni = 0; ni < 8; ni++) {
                int rowm = mw + 16 * mi + lr;
                int cl = (nw >> 1) + 4 * ni + lq;
                float* a = acc[mi][ni];
                float s0 = sqs[rowm * 68 + cl];
                float s1 = sqs[(rowm + 8) * 68 + cl];
                so[cl * 136 + rowm]     = s0 * __fdividef(a[0], a[1]);
                so[cl * 136 + rowm + 8] = s1 * __fdividef(a[2], a[3]);
            }
        }
        __syncthreads();
        float* o = out + (size_t)b * CC * NN;
        #pragma unroll
        for (int r2 = 0; r2 < 8; r2++) {
            int v = tid + r2 * 256;
            int cl = v >> 5, m4 = (v & 31) << 2;
            float4 val = *(float4*)(so + cl * 136 + m4);
            *(float4*)(o + (size_t)(gc0 + cl) * NN + m0 + m4) = val;
        }
    }
}

// ---------------------------------------------------------------------------
// Launch.  Order: 0 prep_all, 1 proj, 2 attn
// ---------------------------------------------------------------------------
extern "C" void kernel_launch(void* const* d_in, const int* in_sizes, int n_in,
                              void* d_out, int out_size) {
    const float* x  = (const float*)d_in[0];
    const float* y  = (const float*)d_in[1];
    const float* Wq = (const float*)d_in[2];
    const float* bq = (const float*)d_in[3];
    const float* Wk = (const float*)d_in[4];
    const float* bk = (const float*)d_in[5];
    const float* Wv = (const float*)d_in[6];
    const float* bv = (const float*)d_in[7];
    const float* pb = (const float*)d_in[8];
    float* out = (float*)d_out;

    static bool attr_done = false;
    if (!attr_done) {
        cudaFuncSetAttribute(gemm_f16<0>,
                             cudaFuncAttributeMaxDynamicSharedMemorySize, GEMM_SMEM);
        cudaFuncSetAttribute(gemm_f16<1>,
                             cudaFuncAttributeMaxDynamicSharedMemorySize, GEMM_SMEM);
        attr_done = true;
    }

    // 0) all operand prep in one launch
    prep_all<<<PREP_BLOCKS, 256>>>(x, y, Wq, Wk, Wv, pb);

    // 1) fused projection GEMM -> g_sqh (fp16), g_kv4 (attn B-paired)
    {
        dim3 g(NN / 128, NPROJ / 128, BB);   // (18, 12, 8)
        gemm_f16<0><<<g, 256, GEMM_SMEM>>>(bq, bk, bv, nullptr);
    }

    // 2) attention GEMM + fused final epilogue -> out
    {
        dim3 g(NN / 128, NKV / 128, BB);     // (18, 8, 8)
        gemm_f16<1><<<g, 256, GEMM_SMEM>>>(bq, bk, bv, out);
    }
}

// round 16
// speedup vs baseline: 1.1245x; 1.0584x over previous
#include <cuda_runtime.h>
#include <cuda_fp16.h>
#include <math.h>
#include <stdint.h>

// Problem constants
#define BB 8
#define CC 512
#define NN 2304          // 48*48
#define NPROJ 1536       // q(512) | interleaved k,v (1024)
#define NKV 1024         // interleaved pairs: col 2c=ekv_c, 2c+1=ek_c
#define MGT 144          // NN/16 m-groups
#define KOCT_P 32        // CC/16 k-octs (projection K)
#define KOCT_A 144       // NN/16 k-octs (attention K)
#define NP16_P 96        // NPROJ/16 n-pairs
#define NP16_A 64        // NKV/16 n-pairs

// ---------------------------------------------------------------------------
// Scratch — MMA-native layouts (R10/R12-validated).
// ---------------------------------------------------------------------------
__device__ uint4  g_x4 [(size_t)BB * KOCT_P * MGT * 32];
__device__ uint4  g_y4 [(size_t)BB * KOCT_P * MGT * 32];
__device__ uint4  g_eb4[(size_t)KOCT_A * MGT * 32];
__device__ uint4  g_w4 [(size_t)KOCT_P * NP16_P * 32];
__device__ uint4  g_kv4[(size_t)BB * KOCT_A * NP16_A * 32];
__device__ __half g_sqh[(size_t)BB * NN * CC];   // sigmoid(q) fp16 [b][i][c]

// ---------------------------------------------------------------------------
// Helpers
// ---------------------------------------------------------------------------
__device__ __forceinline__ uint32_t packh2(float lo, float hi) {
    __half2 h = __floats2half2_rn(lo, hi);
    return *reinterpret_cast<uint32_t*>(&h);
}

__device__ __forceinline__ void mma_f16(float c[4], const uint32_t* a,
                                        const uint32_t* b) {
    asm volatile(
        "mma.sync.aligned.m16n8k16.row.col.f32.f16.f16.f32 "
        "{%0,%1,%2,%3},{%4,%5,%6,%7},{%8,%9},{%0,%1,%2,%3};\n"
        : "+f"(c[0]), "+f"(c[1]), "+f"(c[2]), "+f"(c[3])
        : "r"(a[0]), "r"(a[1]), "r"(a[2]), "r"(a[3]), "r"(b[0]), "r"(b[1]));
}

__device__ __forceinline__ uint32_t smem_u32(const void* p) {
    uint32_t a;
    asm("{ .reg .u64 t; cvta.to.shared.u64 t, %1; cvt.u32.u64 %0, t; }"
        : "=r"(a) : "l"(p));
    return a;
}

__device__ __forceinline__ void cp16(uint32_t saddr, const void* gptr) {
    asm volatile("cp.async.cg.shared.global [%0], [%1], 16;"
                 :: "r"(saddr), "l"(gptr));
}
#define CP_COMMIT() asm volatile("cp.async.commit_group;" ::: "memory")
#define CP_WAIT(n)  asm volatile("cp.async.wait_group %0;" :: "n"(n) : "memory")

// ---------------------------------------------------------------------------
// prep_all (fused): 2 k-octs per block for x/y/eb (MLP=4 per thread).
// Block ranges:
//   [0,2304) x   [2304,4608) y   [4608,4992) W   [4992,6288) exp(pb)
// ---------------------------------------------------------------------------
#define PBLK_X  2304
#define PBLK_W  384
#define PBLK_EB 1296
#define PREP_BLOCKS (2 * PBLK_X + PBLK_W + PBLK_EB)   // 6288

__global__ void __launch_bounds__(256)
prep_all(const float* __restrict__ x, const float* __restrict__ y,
         const float* __restrict__ Wq, const float* __restrict__ Wk,
         const float* __restrict__ Wv, const float* __restrict__ pb) {
    __shared__ float s[32][132];
    const int tid = threadIdx.x;
    const int blk = blockIdx.x;

    if (blk < 2 * PBLK_X) {
        // x/y -> A-native (k = channel), 2 k-octs (32 rows) per block
        const bool isx = blk < PBLK_X;
        const float* src = isx ? x : y;
        uint4* dst = isx ? g_x4 : g_y4;
        int v = isx ? blk : blk - PBLK_X;
        int b = v / 288, rem = v % 288;
        int kb2 = rem / 18, iblk = rem % 18;
        int i0 = iblk * 128, c0 = kb2 * 32;
        #pragma unroll
        for (int r = 0; r < 4; r++) {
            int idx = tid + r * 256;
            int row = idx >> 5, col4 = (idx & 31) << 2;
            float4 f = *(const float4*)(src + ((size_t)(b * CC + c0 + row)) * NN + i0 + col4);
            *(float4*)(&s[row][col4]) = f;
        }
        __syncthreads();
        const int mg = tid >> 5, lane = tid & 31, lr = lane >> 2, lq = lane & 3;
        const int m = mg * 16 + lr;
        #pragma unroll
        for (int t = 0; t < 2; t++) {
            int kb = 16 * t;
            uint4 o;
            o.x = packh2(s[kb + 2 * lq][m],     s[kb + 2 * lq + 1][m]);
            o.y = packh2(s[kb + 2 * lq][m + 8], s[kb + 2 * lq + 1][m + 8]);
            o.z = packh2(s[kb + 2 * lq + 8][m],     s[kb + 2 * lq + 9][m]);
            o.w = packh2(s[kb + 2 * lq + 8][m + 8], s[kb + 2 * lq + 9][m + 8]);
            int koct = kb2 * 2 + t;
            dst[(((size_t)b * KOCT_P + koct) * MGT + iblk * 8 + mg) * 32 + lane] = o;
        }
    } else if (blk < 2 * PBLK_X + PBLK_W) {
        // W -> B-paired, n = q | k,v interleaved
        int idx = (blk - 2 * PBLK_X) * 256 + tid;
        int lane = idx & 31;
        int p    = (idx >> 5) % NP16_P;
        int koct = idx / (NP16_P * 32);
        int lr = lane >> 2, lq = lane & 3;
        int k0 = koct * 16 + 2 * lq;
        auto wval = [&](int n, int kk) -> float {
            const float* W;
            int c;
            if (n < 512) { W = Wq; c = n; }
            else {
                int m = n - 512;
                c = m >> 1;
                W = (m & 1) ? Wv : Wk;
            }
            return W[(size_t)c * CC + kk];
        };
        int ne = p * 16 + lr, no = ne + 8;
        uint4 o;
        o.x = packh2(wval(ne, k0),     wval(ne, k0 + 1));
        o.y = packh2(wval(ne, k0 + 8), wval(ne, k0 + 9));
        o.z = packh2(wval(no, k0),     wval(no, k0 + 1));
        o.w = packh2(wval(no, k0 + 8), wval(no, k0 + 9));
        g_w4[idx] = o;
    } else {
        // exp(pb) -> A-native (m = i, k = j), 2 k-octs (32 j) per block
        int t = blk - (2 * PBLK_X + PBLK_W);
        int kb2 = t / 18, iblk = t % 18;
        int i0 = iblk * 128, j0 = kb2 * 32;
        #pragma unroll
        for (int r = 0; r < 4; r++) {
            int idx = tid + r * 256;
            int irow = idx >> 3, j4 = (idx & 7) << 2;
            float4 f = *(const float4*)(pb + (size_t)(i0 + irow) * NN + j0 + j4);
            s[j4 + 0][irow] = __expf(f.x);
            s[j4 + 1][irow] = __expf(f.y);
            s[j4 + 2][irow] = __expf(f.z);
            s[j4 + 3][irow] = __expf(f.w);
        }
        __syncthreads();
        const int mg = tid >> 5, lane = tid & 31, lr = lane >> 2, lq = lane & 3;
        const int m = mg * 16 + lr;
        #pragma unroll
        for (int tt = 0; tt < 2; tt++) {
            int kb = 16 * tt;
            uint4 o;
            o.x = packh2(s[kb + 2 * lq][m],     s[kb + 2 * lq + 1][m]);
            o.y = packh2(s[kb + 2 * lq][m + 8], s[kb + 2 * lq + 1][m + 8]);
            o.z = packh2(s[kb + 2 * lq + 8][m],     s[kb + 2 * lq + 9][m]);
            o.w = packh2(s[kb + 2 * lq + 8][m + 8], s[kb + 2 * lq + 9][m + 8]);
            int koct = kb2 * 2 + tt;
            g_eb4[((size_t)koct * MGT + iblk * 8 + mg) * 32 + lane] = o;
        }
    }
}

// ---------------------------------------------------------------------------
// fp16 GEMM core: BM=128 BN=128, chunk = 4 k-octs (64 k), 256 thr,
// warps 4(m) x 2(n), warp tile 32x64, 3-stage ring, 2 CTAs/SM.
// Steady loop peeled + unrolled by STG so EVERY stage index is a literal.
// ---------------------------------------------------------------------------
#define STG 3
#define A_ST 16384
#define B_ST 16384
#define GEMM_SMEM (STG * (A_ST + B_ST))   // 98304 B

template <int MODE>
__global__ void __launch_bounds__(256, 2)
gemm_f16(const float* __restrict__ bq, const float* __restrict__ bk,
         const float* __restrict__ bv, float* __restrict__ out) {
    extern __shared__ char smem[];
    const uint32_t smb = smem_u32(smem);

    const int b  = blockIdx.z;
    const int m0 = blockIdx.x * 128;
    const int n0 = blockIdx.y * 128;
    const int tid = threadIdx.x;

    constexpr int NP16 = (MODE == 0) ? NP16_P : NP16_A;
    constexpr int nch  = (MODE == 0) ? KOCT_P / 4 : KOCT_A / 4;   // 8 / 36

    const uint4* Ag;
    const uint4* Bg;
    if (MODE == 0) {
        Ag = ((blockIdx.y < 4) ? g_x4 : g_y4) + (size_t)b * KOCT_P * MGT * 32;
        Bg = g_w4;
    } else {
        Ag = g_eb4;
        Bg = g_kv4 + (size_t)b * KOCT_A * NP16_A * 32;
    }
    const int mg0 = m0 >> 4;
    const int np0 = n0 >> 4;

    const int wid = tid >> 5;
    const int mwg = (wid & 3) * 2;
    const int nw  = (wid >> 2) * 64;
    const int nwp = nw >> 4;
    const int lane = tid & 31;
    const int lq = lane & 3;
    const int lr = lane >> 2;

    // Precomputed per-thread gmem bases (advance by chunk stride each use)
    const uint4* agt = Ag + (size_t)mg0 * 32 + tid;
    const uint4* bgt = Bg + (size_t)np0 * 32 + tid;

    auto loadAsync = [&](int ch, int st) {
        const uint32_t sA = smb + st * A_ST;
        const uint32_t sB = smb + STG * A_ST + st * B_ST;
        #pragma unroll
        for (int r = 0; r < 4; r++) {
            int ko = ch * 4 + r;
            cp16(sA + r * 4096 + tid * 16, agt + (size_t)ko * MGT * 32);
            cp16(sB + r * 4096 + tid * 16, bgt + (size_t)ko * NP16 * 32);
        }
    };

    float acc[2][8][4];
    #pragma unroll
    for (int i = 0; i < 2; i++)
        #pragma unroll
        for (int j = 0; j < 8; j++)
            #pragma unroll
            for (int l = 0; l < 4; l++) acc[i][j][l] = 0.f;

    auto compute = [&](int st) {
        const uint4* As4 = (const uint4*)(smem + st * A_ST);
        const uint4* Bs4 = (const uint4*)(smem + STG * A_ST + st * B_ST);
        #pragma unroll
        for (int ka = 0; ka < 4; ka++) {
            uint4 af0 = As4[ka * 256 + mwg * 32 + lane];
            uint4 af1 = As4[ka * 256 + (mwg + 1) * 32 + lane];
            uint4 bp[4];
            #pragma unroll
            for (int pw = 0; pw < 4; pw++)
                bp[pw] = Bs4[ka * 256 + (nwp + pw) * 32 + lane];
            #pragma unroll
            for (int pw = 0; pw < 4; pw++) {
                mma_f16(acc[0][2 * pw],     (const uint32_t*)&af0, &bp[pw].x);
                mma_f16(acc[0][2 * pw + 1], (const uint32_t*)&af0, &bp[pw].z);
                mma_f16(acc[1][2 * pw],     (const uint32_t*)&af1, &bp[pw].x);
                mma_f16(acc[1][2 * pw + 1], (const uint32_t*)&af1, &bp[pw].z);
            }
        }
    };

    #pragma unroll
    for (int s = 0; s < STG - 1; s++) {
        loadAsync(s, s);
        CP_COMMIT();
    }

    constexpr int steady = nch - (STG - 1);        // 6 / 34
    constexpr int pre    = steady % STG;           // 0 / 1
    constexpr int groups = (steady - pre) / STG;   // 2 / 11

    // Peeled pre-iterations: c = 0..pre-1, literal stages
    #pragma unroll
    for (int c = 0; c < pre; c++) {
        CP_WAIT(STG - 2);
        __syncthreads();
        loadAsync(c + STG - 1, (c + STG - 1) % STG);
        CP_COMMIT();
        compute(c % STG);
    }
    // Grouped steady: inner unrolled by STG, stage = (pre+s±)%STG is a literal
    for (int g = 0; g < groups; g++) {
        const int cbase = pre + g * STG;
        #pragma unroll
        for (int s = 0; s < STG; s++) {
            CP_WAIT(STG - 2);
            __syncthreads();
            loadAsync(cbase + s + STG - 1, (pre + s + STG - 1) % STG);
            CP_COMMIT();
            compute((pre + s) % STG);
        }
    }
    // Tail: drain remaining STG-1 chunks, literal stages
    #pragma unroll
    for (int s = 0; s < STG - 1; s++) {
        CP_WAIT(STG - 2);
        __syncthreads();
        CP_COMMIT();
        compute((steady + s) % STG);
    }

    // ------------------------------- Epilogues -----------------------------
    const int mw = (wid & 3) * 32;
    if (MODE == 0) {
        if (n0 < 512) {
            __half* sq = g_sqh + (size_t)b * NN * CC;
            #pragma unroll
            for (int mi = 0; mi < 2; mi++) {
                #pragma unroll
                for (int ni = 0; ni < 8; ni++) {
                    int row = m0 + mw + 16 * mi + lr;
                    int col = n0 + nw + 8 * ni + 2 * lq;
                    float b0 = bq[col], b1 = bq[col + 1];
                    float* a = acc[mi][ni];
                    float s00 = __fdividef(1.f, 1.f + __expf(-(a[0] + b0)));
                    float s01 = __fdividef(1.f, 1.f + __expf(-(a[1] + b1)));
                    float s10 = __fdividef(1.f, 1.f + __expf(-(a[2] + b0)));
                    float s11 = __fdividef(1.f, 1.f + __expf(-(a[3] + b1)));
                    *(uint32_t*)(sq + (size_t)row * CC + col) = packh2(s00, s01);
                    *(uint32_t*)(sq + (size_t)(row + 8) * CC + col) = packh2(s10, s11);
                }
            }
        } else {
            // kv region -> attn B-paired [koct_j][pair][lane]
            uint4* kvh = g_kv4 + (size_t)b * KOCT_A * NP16_A * 32;
            const bool evenR = (lr & 1) == 0;
            const int t = lr >> 1;
            #pragma unroll
            for (int mi = 0; mi < 2; mi++) {
                int mb = m0 + mw + 16 * mi;
                int koct = mb >> 4;
                #pragma unroll
                for (int np = 0; np < 4; np++) {
                    int col_e = n0 + nw + 16 * np + 2 * lq - 512;
                    int ch_e = col_e >> 1;
                    int ch_o = ch_e + 4;
                    float* ae = acc[mi][2 * np];
                    float* ao = acc[mi][2 * np + 1];
                    float bk_e = bk[ch_e], bv_e = bv[ch_e];
                    float bk_o = bk[ch_o], bv_o = bv[ch_o];
                    float e0e  = __expf(ae[0] + bk_e);
                    float ev0e = e0e * (ae[1] + bv_e);
                    float e1e  = __expf(ae[2] + bk_e);
                    float ev1e = e1e * (ae[3] + bv_e);
                    float e0o  = __expf(ao[0] + bk_o);
                    float ev0o = e0o * (ao[1] + bv_o);
                    float e1o  = __expf(ao[2] + bk_o);
                    float ev1o = e1o * (ao[3] + bv_o);
                    float pe0e  = __shfl_xor_sync(0xffffffffu, e0e, 4);
                    float pev0e = __shfl_xor_sync(0xffffffffu, ev0e, 4);
                    float pe1e  = __shfl_xor_sync(0xffffffffu, e1e, 4);
                    float pev1e = __shfl_xor_sync(0xffffffffu, ev1e, 4);
                    float pe0o  = __shfl_xor_sync(0xffffffffu, e0o, 4);
                    float pev0o = __shfl_xor_sync(0xffffffffu, ev0o, 4);
                    float pe1o  = __shfl_xor_sync(0xffffffffu, e1o, 4);
                    float pev1o = __shfl_xor_sync(0xffffffffu, ev1o, 4);
                    if (evenR) {
                        int p = col_e >> 4;
                        int lane_e = (col_e & 7) * 4 + t;
                        uint4 wkv, wek;
                        wkv.x = packh2(ev0e, pev0e);
                        wkv.y = packh2(ev1e, pev1e);
                        wkv.z = packh2(ev0o, pev0o);
                        wkv.w = packh2(ev1o, pev1o);
                        wek.x = packh2(e0e, pe0e);
                        wek.y = packh2(e1e, pe1e);
                        wek.z = packh2(e0o, pe0o);
                        wek.w = packh2(e1o, pe1o);
                        kvh[((size_t)koct * NP16_A + p) * 32 + lane_e]     = wkv;
                        kvh[((size_t)koct * NP16_A + p) * 32 + lane_e + 4] = wek;
                    }
                }
            }
        }
    } else {
        // attn: even col = num, odd = den -> sq * num/den -> transpose -> out
        __syncthreads();
        float* so  = (float*)smem;               // [c_local 0..63][m 0..127] str 136
        float* sqs = (float*)(smem + 34816);     // [m 0..127][c_local 0..63] str 68
        const int gc0 = n0 >> 1;
        const __half* sqg = g_sqh + ((size_t)b * NN + m0) * CC + gc0;
        #pragma unroll
        for (int r2 = 0; r2 < 4; r2++) {
            int v = tid + r2 * 256;
            int row = v >> 3, c8 = (v & 7) * 8;
            uint4 h = *(const uint4*)(sqg + (size_t)row * CC + c8);
            const __half2* hp = (const __half2*)&h;
            float* dstp = sqs + row * 68 + c8;
            #pragma unroll
            for (int q = 0; q < 4; q++) {
                float2 f = __half22float2(hp[q]);
                dstp[2 * q]     = f.x;
                dstp[2 * q + 1] = f.y;
            }
        }
        __syncthreads();
        #pragma unroll
        for (int mi = 0; mi < 2; mi++) {
            #pragma unroll
            for (int ni = 0; ni < 8; ni++) {
                int rowm = mw + 16 * mi + lr;
                int cl = (nw >> 1) + 4 * ni + lq;
                float* a = acc[mi][ni];
                float s0 = sqs[rowm * 68 + cl];
                float s1 = sqs[(rowm + 8) * 68 + cl];
                so[cl * 136 + rowm]     = s0 * __fdividef(a[0], a[1]);
                so[cl * 136 + rowm + 8] = s1 * __fdividef(a[2], a[3]);
            }
        }
        __syncthreads();
        float* o = out + (size_t)b * CC * NN;
        #pragma unroll
        for (int r2 = 0; r2 < 8; r2++) {
            int v = tid + r2 * 256;
            int cl = v >> 5, m4 = (v & 31) << 2;
            float4 val = *(float4*)(so + cl * 136 + m4);
            *(float4*)(o + (size_t)(gc0 + cl) * NN + m0 + m4) = val;
        }
    }
}

// ---------------------------------------------------------------------------
// Launch.  Order: 0 prep_all, 1 proj, 2 attn
// ---------------------------------------------------------------------------
extern "C" void kernel_launch(void* const* d_in, const int* in_sizes, int n_in,
                              void* d_out, int out_size) {
    const float* x  = (const float*)d_in[0];
    const float* y  = (const float*)d_in[1];
    const float* Wq = (const float*)d_in[2];
    const float* bq = (const float*)d_in[3];
    const float* Wk = (const float*)d_in[4];
    const float* bk = (const float*)d_in[5];
    const float* Wv = (const float*)d_in[6];
    const float* bv = (const float*)d_in[7];
    const float* pb = (const float*)d_in[8];
    float* out = (float*)d_out;

    static bool attr_done = false;
    if (!attr_done) {
        cudaFuncSetAttribute(gemm_f16<0>,
                             cudaFuncAttributeMaxDynamicSharedMemorySize, GEMM_SMEM);
        cudaFuncSetAttribute(gemm_f16<1>,
                             cudaFuncAttributeMaxDynamicSharedMemorySize, GEMM_SMEM);
        attr_done = true;
    }

    // 0) all operand prep in one launch
    prep_all<<<PREP_BLOCKS, 256>>>(x, y, Wq, Wk, Wv, pb);

    // 1) fused projection GEMM -> g_sqh (fp16), g_kv4 (attn B-paired)
    {
        dim3 g(NN / 128, NPROJ / 128, BB);   // (18, 12, 8)
        gemm_f16<0><<<g, 256, GEMM_SMEM>>>(bq, bk, bv, nullptr);
    }

    // 2) attention GEMM + fused final epilogue -> out
    {
        dim3 g(NN / 128, NKV / 128, BB);     // (18, 8, 8)
        gemm_f16<1><<<g, 256, GEMM_SMEM>>>(bq, bk, bv, out);
    }
}

// round 17
// speedup vs baseline: 1.1482x; 1.0210x over previous
#include <cuda_runtime.h>
#include <cuda_fp16.h>
#include <math.h>
#include <stdint.h>

// Problem constants
#define BB 8
#define CC 512
#define NN 2304          // 48*48
#define NPROJ 1536       // q(512) | interleaved k,v (1024)
#define NKV 1024         // interleaved pairs: col 2c=ekv_c, 2c+1=ek_c
#define MGT 144          // NN/16 m-groups
#define KOCT_P 32        // CC/16 k-octs (projection K)
#define KOCT_A 144       // NN/16 k-octs (attention K)
#define NP16_P 96        // NPROJ/16 n-pairs
#define NP16_A 64        // NKV/16 n-pairs

// ---------------------------------------------------------------------------
// Scratch — MMA-native layouts (R10/R12-validated).
// ---------------------------------------------------------------------------
__device__ uint4  g_x4 [(size_t)BB * KOCT_P * MGT * 32];
__device__ uint4  g_y4 [(size_t)BB * KOCT_P * MGT * 32];
__device__ uint4  g_eb4[(size_t)KOCT_A * MGT * 32];
__device__ uint4  g_w4 [(size_t)KOCT_P * NP16_P * 32];
__device__ uint4  g_kv4[(size_t)BB * KOCT_A * NP16_A * 32];
__device__ __half g_sqh[(size_t)BB * NN * CC];   // sigmoid(q) fp16 [b][i][c]

// ---------------------------------------------------------------------------
// Helpers
// ---------------------------------------------------------------------------
__device__ __forceinline__ uint32_t packh2(float lo, float hi) {
    __half2 h = __floats2half2_rn(lo, hi);
    return *reinterpret_cast<uint32_t*>(&h);
}

__device__ __forceinline__ void mma_f16(float c[4], const uint32_t* a,
                                        const uint32_t* b) {
    asm volatile(
        "mma.sync.aligned.m16n8k16.row.col.f32.f16.f16.f32 "
        "{%0,%1,%2,%3},{%4,%5,%6,%7},{%8,%9},{%0,%1,%2,%3};\n"
        : "+f"(c[0]), "+f"(c[1]), "+f"(c[2]), "+f"(c[3])
        : "r"(a[0]), "r"(a[1]), "r"(a[2]), "r"(a[3]), "r"(b[0]), "r"(b[1]));
}

__device__ __forceinline__ uint32_t smem_u32(const void* p) {
    uint32_t a;
    asm("{ .reg .u64 t; cvta.to.shared.u64 t, %1; cvt.u32.u64 %0, t; }"
        : "=r"(a) : "l"(p));
    return a;
}

__device__ __forceinline__ void cp16(uint32_t saddr, const void* gptr) {
    asm volatile("cp.async.cg.shared.global [%0], [%1], 16;"
                 :: "r"(saddr), "l"(gptr));
}
#define CP_COMMIT() asm volatile("cp.async.commit_group;" ::: "memory")
#define CP_WAIT(n)  asm volatile("cp.async.wait_group %0;" :: "n"(n) : "memory")

// ---------------------------------------------------------------------------
// prep_all (fused): 2 k-octs per block for x/y/eb (MLP=4 per thread).
// Block ranges:
//   [0,2304) x   [2304,4608) y   [4608,4992) W   [4992,6288) exp(pb)
// ---------------------------------------------------------------------------
#define PBLK_X  2304
#define PBLK_W  384
#define PBLK_EB 1296
#define PREP_BLOCKS (2 * PBLK_X + PBLK_W + PBLK_EB)   // 6288

__global__ void __launch_bounds__(256)
prep_all(const float* __restrict__ x, const float* __restrict__ y,
         const float* __restrict__ Wq, const float* __restrict__ Wk,
         const float* __restrict__ Wv, const float* __restrict__ pb) {
    __shared__ float s[32][132];
    const int tid = threadIdx.x;
    const int blk = blockIdx.x;

    if (blk < 2 * PBLK_X) {
        // x/y -> A-native (k = channel), 2 k-octs (32 rows) per block
        const bool isx = blk < PBLK_X;
        const float* src = isx ? x : y;
        uint4* dst = isx ? g_x4 : g_y4;
        int v = isx ? blk : blk - PBLK_X;
        int b = v / 288, rem = v % 288;
        int kb2 = rem / 18, iblk = rem % 18;
        int i0 = iblk * 128, c0 = kb2 * 32;
        #pragma unroll
        for (int r = 0; r < 4; r++) {
            int idx = tid + r * 256;
            int row = idx >> 5, col4 = (idx & 31) << 2;
            float4 f = *(const float4*)(src + ((size_t)(b * CC + c0 + row)) * NN + i0 + col4);
            *(float4*)(&s[row][col4]) = f;
        }
        __syncthreads();
        const int mg = tid >> 5, lane = tid & 31, lr = lane >> 2, lq = lane & 3;
        const int m = mg * 16 + lr;
        #pragma unroll
        for (int t = 0; t < 2; t++) {
            int kb = 16 * t;
            uint4 o;
            o.x = packh2(s[kb + 2 * lq][m],     s[kb + 2 * lq + 1][m]);
            o.y = packh2(s[kb + 2 * lq][m + 8], s[kb + 2 * lq + 1][m + 8]);
            o.z = packh2(s[kb + 2 * lq + 8][m],     s[kb + 2 * lq + 9][m]);
            o.w = packh2(s[kb + 2 * lq + 8][m + 8], s[kb + 2 * lq + 9][m + 8]);
            int koct = kb2 * 2 + t;
            dst[(((size_t)b * KOCT_P + koct) * MGT + iblk * 8 + mg) * 32 + lane] = o;
        }
    } else if (blk < 2 * PBLK_X + PBLK_W) {
        // W -> B-paired, n = q | k,v interleaved
        int idx = (blk - 2 * PBLK_X) * 256 + tid;
        int lane = idx & 31;
        int p    = (idx >> 5) % NP16_P;
        int koct = idx / (NP16_P * 32);
        int lr = lane >> 2, lq = lane & 3;
        int k0 = koct * 16 + 2 * lq;
        auto wval = [&](int n, int kk) -> float {
            const float* W;
            int c;
            if (n < 512) { W = Wq; c = n; }
            else {
                int m = n - 512;
                c = m >> 1;
                W = (m & 1) ? Wv : Wk;
            }
            return W[(size_t)c * CC + kk];
        };
        int ne = p * 16 + lr, no = ne + 8;
        uint4 o;
        o.x = packh2(wval(ne, k0),     wval(ne, k0 + 1));
        o.y = packh2(wval(ne, k0 + 8), wval(ne, k0 + 9));
        o.z = packh2(wval(no, k0),     wval(no, k0 + 1));
        o.w = packh2(wval(no, k0 + 8), wval(no, k0 + 9));
        g_w4[idx] = o;
    } else {
        // exp(pb) -> A-native (m = i, k = j), 2 k-octs (32 j) per block
        int t = blk - (2 * PBLK_X + PBLK_W);
        int kb2 = t / 18, iblk = t % 18;
        int i0 = iblk * 128, j0 = kb2 * 32;
        #pragma unroll
        for (int r = 0; r < 4; r++) {
            int idx = tid + r * 256;
            int irow = idx >> 3, j4 = (idx & 7) << 2;
            float4 f = *(const float4*)(pb + (size_t)(i0 + irow) * NN + j0 + j4);
            s[j4 + 0][irow] = __expf(f.x);
            s[j4 + 1][irow] = __expf(f.y);
            s[j4 + 2][irow] = __expf(f.z);
            s[j4 + 3][irow] = __expf(f.w);
        }
        __syncthreads();
        const int mg = tid >> 5, lane = tid & 31, lr = lane >> 2, lq = lane & 3;
        const int m = mg * 16 + lr;
        #pragma unroll
        for (int tt = 0; tt < 2; tt++) {
            int kb = 16 * tt;
            uint4 o;
            o.x = packh2(s[kb + 2 * lq][m],     s[kb + 2 * lq + 1][m]);
            o.y = packh2(s[kb + 2 * lq][m + 8], s[kb + 2 * lq + 1][m + 8]);
            o.z = packh2(s[kb + 2 * lq + 8][m],     s[kb + 2 * lq + 9][m]);
            o.w = packh2(s[kb + 2 * lq + 8][m + 8], s[kb + 2 * lq + 9][m + 8]);
            int koct = kb2 * 2 + tt;
            g_eb4[((size_t)koct * MGT + iblk * 8 + mg) * 32 + lane] = o;
        }
    }
}

// ---------------------------------------------------------------------------
// fp16 GEMM core: BM=128 BN=128, chunk = 4 k-octs (64 k), 256 thr,
// warps 4(m) x 2(n), warp tile 32x64, 3-stage ring, 2 CTAs/SM.
// All stage indices are compile-time literals (R16-validated).
// MODE 1: sq tile prefetched via cp.async (rides chunk-0 group) into a
// 16KB XOR-swizzled fp16 smem region; epilogue is sync-free with direct
// coalesced global stores.
// ---------------------------------------------------------------------------
#define STG 3
#define A_ST 16384
#define B_ST 16384
#define SQ_OFF (STG * (A_ST + B_ST))          // 98304
#define GEMM_SMEM (SQ_OFF + 16384)            // 114688 = 14 x 8KB

template <int MODE>
__global__ void __launch_bounds__(256, 2)
gemm_f16(const float* __restrict__ bq, const float* __restrict__ bk,
         const float* __restrict__ bv, float* __restrict__ out) {
    extern __shared__ char smem[];
    const uint32_t smb = smem_u32(smem);

    const int b  = blockIdx.z;
    const int m0 = blockIdx.x * 128;
    const int n0 = blockIdx.y * 128;
    const int tid = threadIdx.x;

    constexpr int NP16 = (MODE == 0) ? NP16_P : NP16_A;
    constexpr int nch  = (MODE == 0) ? KOCT_P / 4 : KOCT_A / 4;   // 8 / 36

    const uint4* Ag;
    const uint4* Bg;
    if (MODE == 0) {
        Ag = ((blockIdx.y < 4) ? g_x4 : g_y4) + (size_t)b * KOCT_P * MGT * 32;
        Bg = g_w4;
    } else {
        Ag = g_eb4;
        Bg = g_kv4 + (size_t)b * KOCT_A * NP16_A * 32;
    }
    const int mg0 = m0 >> 4;
    const int np0 = n0 >> 4;

    const int wid = tid >> 5;
    const int mwg = (wid & 3) * 2;
    const int nw  = (wid >> 2) * 64;
    const int nwp = nw >> 4;
    const int lane = tid & 31;
    const int lq = lane & 3;
    const int lr = lane >> 2;

    const uint4* agt = Ag + (size_t)mg0 * 32 + tid;
    const uint4* bgt = Bg + (size_t)np0 * 32 + tid;

    auto loadAsync = [&](int ch, int st) {
        const uint32_t sA = smb + st * A_ST;
        const uint32_t sB = smb + STG * A_ST + st * B_ST;
        #pragma unroll
        for (int r = 0; r < 4; r++) {
            int ko = ch * 4 + r;
            cp16(sA + r * 4096 + tid * 16, agt + (size_t)ko * MGT * 32);
            cp16(sB + r * 4096 + tid * 16, bgt + (size_t)ko * NP16 * 32);
        }
    };

    float acc[2][8][4];
    #pragma unroll
    for (int i = 0; i < 2; i++)
        #pragma unroll
        for (int j = 0; j < 8; j++)
            #pragma unroll
            for (int l = 0; l < 4; l++) acc[i][j][l] = 0.f;

    auto compute = [&](int st) {
        const uint4* As4 = (const uint4*)(smem + st * A_ST);
        const uint4* Bs4 = (const uint4*)(smem + STG * A_ST + st * B_ST);
        #pragma unroll
        for (int ka = 0; ka < 4; ka++) {
            uint4 af0 = As4[ka * 256 + mwg * 32 + lane];
            uint4 af1 = As4[ka * 256 + (mwg + 1) * 32 + lane];
            uint4 bp[4];
            #pragma unroll
            for (int pw = 0; pw < 4; pw++)
                bp[pw] = Bs4[ka * 256 + (nwp + pw) * 32 + lane];
            #pragma unroll
            for (int pw = 0; pw < 4; pw++) {
                mma_f16(acc[0][2 * pw],     (const uint32_t*)&af0, &bp[pw].x);
                mma_f16(acc[0][2 * pw + 1], (const uint32_t*)&af0, &bp[pw].z);
                mma_f16(acc[1][2 * pw],     (const uint32_t*)&af1, &bp[pw].x);
                mma_f16(acc[1][2 * pw + 1], (const uint32_t*)&af1, &bp[pw].z);
            }
        }
    };

    // sq prefetch (MODE 1): 128 rows x 64 fp16 = 16KB, XOR-swizzled 16B chunks.
    // Issued before chunk-0's commit -> completes with the first CP_WAIT.
    if (MODE == 1) {
        const __half* sqg = g_sqh + ((size_t)b * NN + m0) * CC + (n0 >> 1);
        #pragma unroll
        for (int r = 0; r < 4; r++) {
            int v = tid + r * 256;
            int row = v >> 3, c16 = v & 7;
            cp16(smb + SQ_OFF + row * 128 + ((c16 ^ (row & 7)) << 4),
                 sqg + (size_t)row * CC + c16 * 8);
        }
    }
    #pragma unroll
    for (int s = 0; s < STG - 1; s++) {
        loadAsync(s, s);
        CP_COMMIT();
    }

    constexpr int steady = nch - (STG - 1);        // 6 / 34
    constexpr int pre    = steady % STG;           // 0 / 1
    constexpr int groups = (steady - pre) / STG;   // 2 / 11

    #pragma unroll
    for (int c = 0; c < pre; c++) {
        CP_WAIT(STG - 2);
        __syncthreads();
        loadAsync(c + STG - 1, (c + STG - 1) % STG);
        CP_COMMIT();
        compute(c % STG);
    }
    for (int g = 0; g < groups; g++) {
        const int cbase = pre + g * STG;
        #pragma unroll
        for (int s = 0; s < STG; s++) {
            CP_WAIT(STG - 2);
            __syncthreads();
            loadAsync(cbase + s + STG - 1, (pre + s + STG - 1) % STG);
            CP_COMMIT();
            compute((pre + s) % STG);
        }
    }
    #pragma unroll
    for (int s = 0; s < STG - 1; s++) {
        CP_WAIT(STG - 2);
        __syncthreads();
        CP_COMMIT();
        compute((steady + s) % STG);
    }

    // ------------------------------- Epilogues -----------------------------
    const int mw = (wid & 3) * 32;
    if (MODE == 0) {
        if (n0 < 512) {
            __half* sq = g_sqh + (size_t)b * NN * CC;
            #pragma unroll
            for (int mi = 0; mi < 2; mi++) {
                #pragma unroll
                for (int ni = 0; ni < 8; ni++) {
                    int row = m0 + mw + 16 * mi + lr;
                    int col = n0 + nw + 8 * ni + 2 * lq;
                    float b0 = bq[col], b1 = bq[col + 1];
                    float* a = acc[mi][ni];
                    float s00 = __fdividef(1.f, 1.f + __expf(-(a[0] + b0)));
                    float s01 = __fdividef(1.f, 1.f + __expf(-(a[1] + b1)));
                    float s10 = __fdividef(1.f, 1.f + __expf(-(a[2] + b0)));
                    float s11 = __fdividef(1.f, 1.f + __expf(-(a[3] + b1)));
                    *(uint32_t*)(sq + (size_t)row * CC + col) = packh2(s00, s01);
                    *(uint32_t*)(sq + (size_t)(row + 8) * CC + col) = packh2(s10, s11);
                }
            }
        } else {
            // kv region -> attn B-paired [koct_j][pair][lane]
            uint4* kvh = g_kv4 + (size_t)b * KOCT_A * NP16_A * 32;
            const bool evenR = (lr & 1) == 0;
            const int t = lr >> 1;
            #pragma unroll
            for (int mi = 0; mi < 2; mi++) {
                int mb = m0 + mw + 16 * mi;
                int koct = mb >> 4;
                #pragma unroll
                for (int np = 0; np < 4; np++) {
                    int col_e = n0 + nw + 16 * np + 2 * lq - 512;
                    int ch_e = col_e >> 1;
                    int ch_o = ch_e + 4;
                    float* ae = acc[mi][2 * np];
                    float* ao = acc[mi][2 * np + 1];
                    float bk_e = bk[ch_e], bv_e = bv[ch_e];
                    float bk_o = bk[ch_o], bv_o = bv[ch_o];
                    float e0e  = __expf(ae[0] + bk_e);
                    float ev0e = e0e * (ae[1] + bv_e);
                    float e1e  = __expf(ae[2] + bk_e);
                    float ev1e = e1e * (ae[3] + bv_e);
                    float e0o  = __expf(ao[0] + bk_o);
                    float ev0o = e0o * (ao[1] + bv_o);
                    float e1o  = __expf(ao[2] + bk_o);
                    float ev1o = e1o * (ao[3] + bv_o);
                    float pe0e  = __shfl_xor_sync(0xffffffffu, e0e, 4);
                    float pev0e = __shfl_xor_sync(0xffffffffu, ev0e, 4);
                    float pe1e  = __shfl_xor_sync(0xffffffffu, e1e, 4);
                    float pev1e = __shfl_xor_sync(0xffffffffu, ev1e, 4);
                    float pe0o  = __shfl_xor_sync(0xffffffffu, e0o, 4);
                    float pev0o = __shfl_xor_sync(0xffffffffu, ev0o, 4);
                    float pe1o  = __shfl_xor_sync(0xffffffffu, e1o, 4);
                    float pev1o = __shfl_xor_sync(0xffffffffu, ev1o, 4);
                    if (evenR) {
                        int p = col_e >> 4;
                        int lane_e = (col_e & 7) * 4 + t;
                        uint4 wkv, wek;
                        wkv.x = packh2(ev0e, pev0e);
                        wkv.y = packh2(ev1e, pev1e);
                        wkv.z = packh2(ev0o, pev0o);
                        wkv.w = packh2(ev1o, pev1o);
                        wek.x = packh2(e0e, pe0e);
                        wek.y = packh2(e1e, pe1e);
                        wek.z = packh2(e0o, pe0o);
                        wek.w = packh2(e1o, pe1o);
                        kvh[((size_t)koct * NP16_A + p) * 32 + lane_e]     = wkv;
                        kvh[((size_t)koct * NP16_A + p) * 32 + lane_e + 4] = wek;
                    }
                }
            }
        }
    } else {
        // attn: even col = num, odd = den.  sq already in swizzled smem.
        // Direct coalesced stores: per (mi,ni) a warp writes 4 cols x 8
        // consecutive i = four full 32B sectors.  No syncs needed.
        const __half* sqs = (const __half*)(smem + SQ_OFF);
        const int gc0 = n0 >> 1;
        float* o = out + (size_t)b * CC * NN + m0;
        #pragma unroll
        for (int mi = 0; mi < 2; mi++) {
            #pragma unroll
            for (int ni = 0; ni < 8; ni++) {
                int r0 = mw + 16 * mi + lr;
                int r1 = r0 + 8;
                int cl = (nw >> 1) + 4 * ni + lq;
                float* a = acc[mi][ni];
                int chs = ((cl >> 3) ^ (r0 & 7)) << 3;   // r0&7 == r1&7
                float s0 = __half2float(sqs[r0 * 64 + chs + (cl & 7)]);
                float s1 = __half2float(sqs[r1 * 64 + chs + (cl & 7)]);
                float* oc = o + (size_t)(gc0 + cl) * NN;
                oc[r0] = s0 * __fdividef(a[0], a[1]);
                oc[r1] = s1 * __fdividef(a[2], a[3]);
            }
        }
    }
}

// ---------------------------------------------------------------------------
// Launch.  Order: 0 prep_all, 1 proj, 2 attn
// ---------------------------------------------------------------------------
extern "C" void kernel_launch(void* const* d_in, const int* in_sizes, int n_in,
                              void* d_out, int out_size) {
    const float* x  = (const float*)d_in[0];
    const float* y  = (const float*)d_in[1];
    const float* Wq = (const float*)d_in[2];
    const float* bq = (const float*)d_in[3];
    const float* Wk = (const float*)d_in[4];
    const float* bk = (const float*)d_in[5];
    const float* Wv = (const float*)d_in[6];
    const float* bv = (const float*)d_in[7];
    const float* pb = (const float*)d_in[8];
    float* out = (float*)d_out;

    static bool attr_done = false;
    if (!attr_done) {
        cudaFuncSetAttribute(gemm_f16<0>,
                             cudaFuncAttributeMaxDynamicSharedMemorySize, GEMM_SMEM);
        cudaFuncSetAttribute(gemm_f16<1>,
                             cudaFuncAttributeMaxDynamicSharedMemorySize, GEMM_SMEM);
        attr_done = true;
    }

    // 0) all operand prep in one launch
    prep_all<<<PREP_BLOCKS, 256>>>(x, y, Wq, Wk, Wv, pb);

    // 1) fused projection GEMM -> g_sqh (fp16), g_kv4 (attn B-paired)
    {
        dim3 g(NN / 128, NPROJ / 128, BB);   // (18, 12, 8)
        gemm_f16<0><<<g, 256, GEMM_SMEM>>>(bq, bk, bv, nullptr);
    }

    // 2) attention GEMM + fused final epilogue -> out
    {
        dim3 g(NN / 128, NKV / 128, BB);     // (18, 8, 8)
        gemm_f16<1><<<g, 256, GEMM_SMEM>>>(bq, bk, bv, out);
    }
}